// round 9
// baseline (speedup 1.0000x reference)
#include <cuda_runtime.h>
#include <cuda_bf16.h>
#include <math.h>
#include <stdint.h>

// B=4, N=512, D=1024, H=16, HD=64, HID=4096, RP_HID=64; tokens M=2048

#define TEPI_BIASP   0
#define TEPI_GELUP   1
#define TEPI_RESGATE 2
#define TEPI_SCORES  3

// ---------------- scratch ----------------
__device__ float g_mod[4 * 6144];
__device__ float g_att[4 * 16 * 512 * 512];
__device__ float g_x1[2048 * 1024];
__device__ __nv_bfloat16 g_xnh[2048 * 1024], g_xnl[2048 * 1024];
__device__ __nv_bfloat16 g_qkvph[2048 * 3072], g_qkvpl[2048 * 3072];
__device__ __nv_bfloat16 g_ph[64 * 512 * 512], g_pl[64 * 512 * 512];
__device__ __nv_bfloat16 g_aoh[2048 * 1024], g_aol[2048 * 1024];
__device__ __nv_bfloat16 g_hh[2048 * 4096], g_hl[2048 * 4096];
__device__ __nv_bfloat16 g_wqkvh[3072 * 1024], g_wqkvl[3072 * 1024];
__device__ __nv_bfloat16 g_wprojh[1024 * 1024], g_wprojl[1024 * 1024];
__device__ __nv_bfloat16 g_wfc1h[4096 * 1024], g_wfc1l[4096 * 1024];
__device__ __nv_bfloat16 g_wfc2h[1024 * 4096], g_wfc2l[1024 * 4096];

// ---------------- helpers ----------------
__device__ __forceinline__ uint32_t smem_u32(const void* p) {
    uint32_t a;
    asm("{ .reg .u64 t; cvta.to.shared.u64 t, %1; cvt.u32.u64 %0, t; }" : "=r"(a) : "l"(p));
    return a;
}
__device__ __forceinline__ void cp16(uint32_t s, const void* g) {
    asm volatile("cp.async.cg.shared.global [%0], [%1], 16;" :: "r"(s), "l"(g));
}
__device__ __forceinline__ void cp_commit() {
    asm volatile("cp.async.commit_group;" ::: "memory");
}
__device__ __forceinline__ void cp_wait0() {
    asm volatile("cp.async.wait_group 0;" ::: "memory");
}
__device__ __forceinline__ void cp_wait1() {
    asm volatile("cp.async.wait_group 1;" ::: "memory");
}
__device__ __forceinline__ void ldmat4(uint32_t& r0, uint32_t& r1, uint32_t& r2, uint32_t& r3, uint32_t a) {
    asm volatile("ldmatrix.sync.aligned.m8n8.x4.shared.b16 {%0,%1,%2,%3}, [%4];"
                 : "=r"(r0), "=r"(r1), "=r"(r2), "=r"(r3) : "r"(a));
}
__device__ __forceinline__ void ldmat4t(uint32_t& r0, uint32_t& r1, uint32_t& r2, uint32_t& r3, uint32_t a) {
    asm volatile("ldmatrix.sync.aligned.m8n8.x4.trans.shared.b16 {%0,%1,%2,%3}, [%4];"
                 : "=r"(r0), "=r"(r1), "=r"(r2), "=r"(r3) : "r"(a));
}
__device__ __forceinline__ void mma16816(float* c, const uint32_t* a, uint32_t b0, uint32_t b1) {
    asm volatile(
        "mma.sync.aligned.m16n8k16.row.col.f32.bf16.bf16.f32 "
        "{%0,%1,%2,%3}, {%4,%5,%6,%7}, {%8,%9}, {%0,%1,%2,%3};"
        : "+f"(c[0]), "+f"(c[1]), "+f"(c[2]), "+f"(c[3])
        : "r"(a[0]), "r"(a[1]), "r"(a[2]), "r"(a[3]), "r"(b0), "r"(b1));
}

// ---------------- adaLN ----------------
__global__ __launch_bounds__(256) void ada_kernel(
    const float* __restrict__ t_emb, const float* __restrict__ w_ada,
    const float* __restrict__ b_ada, float* __restrict__ mod)
{
    __shared__ float sh[4096];
    int tid = threadIdx.x;
    for (int i = tid; i < 4096; i += 256) {
        float t = t_emb[i];
        sh[i] = t / (1.0f + __expf(-t));
    }
    __syncthreads();
    int j = blockIdx.x * 8 + (tid >> 5);
    int lane = tid & 31;
    const float* wr = w_ada + (size_t)j * 1024;
    float a0 = 0.f, a1 = 0.f, a2 = 0.f, a3 = 0.f;
    for (int k = lane; k < 1024; k += 32) {
        float w = wr[k];
        a0 = fmaf(w, sh[k], a0);
        a1 = fmaf(w, sh[1024 + k], a1);
        a2 = fmaf(w, sh[2048 + k], a2);
        a3 = fmaf(w, sh[3072 + k], a3);
    }
    for (int o = 16; o; o >>= 1) {
        a0 += __shfl_xor_sync(0xffffffffu, a0, o);
        a1 += __shfl_xor_sync(0xffffffffu, a1, o);
        a2 += __shfl_xor_sync(0xffffffffu, a2, o);
        a3 += __shfl_xor_sync(0xffffffffu, a3, o);
    }
    if (lane == 0) {
        float bb = b_ada[j];
        mod[j]            = a0 + bb;
        mod[6144 + j]     = a1 + bb;
        mod[2 * 6144 + j] = a2 + bb;
        mod[3 * 6144 + j] = a3 + bb;
    }
}

// ---------------- LN + modulation -> bf16 pair ----------------
__global__ __launch_bounds__(256) void ln_mod_kernel(
    const float* __restrict__ xin, const float* __restrict__ gamma,
    const float* __restrict__ beta, const float* __restrict__ mod,
    int shift_chunk, int scale_chunk,
    __nv_bfloat16* __restrict__ outh, __nv_bfloat16* __restrict__ outl)
{
    int token = blockIdx.x;
    int b = token >> 9;
    int tid = threadIdx.x;
    const float* xr = xin + (size_t)token * 1024;
    float v[4];
    float s = 0.f, sq = 0.f;
#pragma unroll
    for (int i = 0; i < 4; i++) {
        float t = xr[i * 256 + tid];
        v[i] = t; s += t; sq += t * t;
    }
    for (int o = 16; o; o >>= 1) {
        s  += __shfl_xor_sync(0xffffffffu, s, o);
        sq += __shfl_xor_sync(0xffffffffu, sq, o);
    }
    __shared__ float ss[8], ssq[8], smu, srstd;
    int wid = tid >> 5, lane = tid & 31;
    if (lane == 0) { ss[wid] = s; ssq[wid] = sq; }
    __syncthreads();
    if (tid == 0) {
        float S = 0.f, Q = 0.f;
        for (int i = 0; i < 8; i++) { S += ss[i]; Q += ssq[i]; }
        float mu = S * (1.0f / 1024.0f);
        float var = Q * (1.0f / 1024.0f) - mu * mu;
        smu = mu; srstd = rsqrtf(var + 1e-5f);
    }
    __syncthreads();
    float mu = smu, rstd = srstd;
    const float* modb = mod + (size_t)b * 6144;
    const float* shm = modb + shift_chunk * 1024;
    const float* scm = modb + scale_chunk * 1024;
    size_t rb = (size_t)token * 1024;
#pragma unroll
    for (int i = 0; i < 4; i++) {
        int c = i * 256 + tid;
        float ln = (v[i] - mu) * rstd * gamma[c] + beta[c];
        float o = ln * (1.0f + scm[c]) + shm[c];
        __nv_bfloat16 h = __float2bfloat16(o);
        outh[rb + c] = h;
        outl[rb + c] = __float2bfloat16(o - __bfloat162float(h));
    }
}

// ---------------- split fp32 -> bf16 pair (weights) ----------------
__global__ __launch_bounds__(256) void split_kernel(
    const float* __restrict__ src, __nv_bfloat16* __restrict__ hi,
    __nv_bfloat16* __restrict__ lo, int n4)
{
    int i = blockIdx.x * 256 + threadIdx.x;
    if (i >= n4) return;
    float4 v = reinterpret_cast<const float4*>(src)[i];
    __nv_bfloat16 h0 = __float2bfloat16(v.x), h1 = __float2bfloat16(v.y);
    __nv_bfloat16 h2 = __float2bfloat16(v.z), h3 = __float2bfloat16(v.w);
    __nv_bfloat162 H0; H0.x = h0; H0.y = h1;
    __nv_bfloat162 H1; H1.x = h2; H1.y = h3;
    __nv_bfloat162 L0, L1;
    L0.x = __float2bfloat16(v.x - __bfloat162float(h0));
    L0.y = __float2bfloat16(v.y - __bfloat162float(h1));
    L1.x = __float2bfloat16(v.z - __bfloat162float(h2));
    L1.y = __float2bfloat16(v.w - __bfloat162float(h3));
    reinterpret_cast<__nv_bfloat162*>(hi)[2 * i]     = H0;
    reinterpret_cast<__nv_bfloat162*>(hi)[2 * i + 1] = H1;
    reinterpret_cast<__nv_bfloat162*>(lo)[2 * i]     = L0;
    reinterpret_cast<__nv_bfloat162*>(lo)[2 * i + 1] = L1;
}

// ---------------- rel-pos bias MLP ----------------
__global__ __launch_bounds__(256) void relpos_kernel(
    const float* __restrict__ rel, const float* __restrict__ w1,
    const float* __restrict__ b1, const float* __restrict__ w2,
    const float* __restrict__ b2, float* __restrict__ out)
{
    __shared__ float sw1[128], sb1[64], sw2[1024], sb2[16];
    int tid = threadIdx.x;
    if (tid < 128) sw1[tid] = w1[tid];
    if (tid < 64)  sb1[tid] = b1[tid];
    for (int i = tid; i < 1024; i += 256) sw2[i] = w2[i];
    if (tid < 16)  sb2[tid] = b2[tid];
    __syncthreads();
    int gid = blockIdx.x * 256 + tid;
    float r0 = rel[2 * (size_t)gid];
    float r1 = rel[2 * (size_t)gid + 1];
    float h[64];
#pragma unroll
    for (int u = 0; u < 64; u++)
        h[u] = fmaxf(fmaf(sw1[2 * u], r0, fmaf(sw1[2 * u + 1], r1, sb1[u])), 0.0f);
    int b = gid >> 18;
    int rem = gid & 262143;
    size_t base = ((size_t)b << 22) + (size_t)rem;
#pragma unroll
    for (int hh = 0; hh < 16; hh++) {
        float s2 = sb2[hh];
#pragma unroll
        for (int u = 0; u < 64; u++)
            s2 = fmaf(h[u], sw2[hh * 64 + u], s2);
        out[base + ((size_t)hh << 18)] = s2;
    }
}

// ---------------- softmax: fp32 att -> bf16 pair P ----------------
__global__ __launch_bounds__(256) void softmax_kernel(
    const float* __restrict__ att,
    __nv_bfloat16* __restrict__ ph, __nv_bfloat16* __restrict__ pl)
{
    int row = blockIdx.x * 8 + (threadIdx.x >> 5);
    int lane = threadIdx.x & 31;
    const float* p = att + (size_t)row * 512;
    float ev[16];
    float mx = -3.4e38f;
#pragma unroll
    for (int i = 0; i < 16; i++) { ev[i] = p[i * 32 + lane]; mx = fmaxf(mx, ev[i]); }
    for (int o = 16; o; o >>= 1) mx = fmaxf(mx, __shfl_xor_sync(0xffffffffu, mx, o));
    float sum = 0.f;
#pragma unroll
    for (int i = 0; i < 16; i++) { ev[i] = __expf(ev[i] - mx); sum += ev[i]; }
    for (int o = 16; o; o >>= 1) sum += __shfl_xor_sync(0xffffffffu, sum, o);
    float inv = 1.0f / sum;
    size_t rb = (size_t)row * 512;
#pragma unroll
    for (int i = 0; i < 16; i++) {
        float v = ev[i] * inv;
        __nv_bfloat16 h = __float2bfloat16(v);
        ph[rb + i * 32 + lane] = h;
        pl[rb + i * 32 + lane] = __float2bfloat16(v - __bfloat162float(h));
    }
}

// ---------------- HMMA bf16x3 GEMM (NT): C = A[M,K] @ B[N,K]^T ----------------
// CTA 128x128, BK=32, 8 warps of 32x64; K'=3K source-select
// 3-stage cp.async pipeline, 1 __syncthreads per chunk
static constexpr int HG_STG  = 20480;            // A 128x80 + B 128x80
static constexpr int HG_SMEM = 128 * 132 * 4;    // 67584 >= 3*20480 = 61440

template<int EPI>
__global__ __launch_bounds__(256) void hmma_gemm(
    const __nv_bfloat16* __restrict__ Ah, const __nv_bfloat16* __restrict__ Al, int lda,
    const __nv_bfloat16* __restrict__ Bh, const __nv_bfloat16* __restrict__ Bl, int ldb,
    float* __restrict__ C, int ldc, int K, int zdiv,
    long long sAb, long long sAh2, long long sBb, long long sBh2,
    long long sCb, long long sCh2,
    const float* __restrict__ bias, const float* __restrict__ res,
    const float* __restrict__ gate, const int* __restrict__ maskp, float alpha,
    __nv_bfloat16* __restrict__ outh, __nv_bfloat16* __restrict__ outl, int ldo)
{
    extern __shared__ char smem[];
    uint32_t sbase = smem_u32(smem);
    int tid = threadIdx.x;
    int m0 = blockIdx.y * 128;
    int n0 = blockIdx.x * 128;
    int z = blockIdx.z;
    int zb = z / zdiv;
    int zh = z - zb * zdiv;
    Ah += zb * sAb + zh * sAh2;  Al += zb * sAb + zh * sAh2;
    Bh += zb * sBb + zh * sBh2;  Bl += zb * sBb + zh * sBh2;
    if (C) C += zb * sCb + zh * sCh2;

    int w = tid >> 5;
    int lane = tid & 31;
    int wm0 = (w & 3) * 32;
    int wn0 = (w >> 2) * 64;
    int mm = lane >> 3, rr = lane & 7;
    int aRowOff = wm0 + ((mm & 1) << 3) + rr;
    int aByte   = (mm >> 1) << 4;
    int bRowOff = wn0 + ((mm >> 1) << 3) + rr;
    int bByte   = (mm & 1) << 4;

    float acc[2][8][4];
#pragma unroll
    for (int mi = 0; mi < 2; mi++)
#pragma unroll
        for (int ni = 0; ni < 8; ni++)
#pragma unroll
            for (int q = 0; q < 4; q++) acc[mi][ni][q] = 0.0f;

    int nc = (3 * K) >> 5;

    auto load_chunk = [&](int c, int s) {
        int kk = c << 5;
        int blk = (kk >= K) + (kk >= 2 * K);
        int koff = kk - blk * K;
        const __nv_bfloat16* pA = (blk == 1) ? Al : Ah;
        const __nv_bfloat16* pB = (blk == 2) ? Bl : Bh;
        uint32_t sA = sbase + s * HG_STG;
        uint32_t sB = sA + 10240;
#pragma unroll
        for (int u = 0; u < 2; u++) {
            int i = u * 256 + tid;
            int ch = i >> 7, r = i & 127;
            cp16(sA + r * 80 + ch * 16, pA + (size_t)(m0 + r) * lda + koff + ch * 8);
            cp16(sB + r * 80 + ch * 16, pB + (size_t)(n0 + r) * ldb + koff + ch * 8);
        }
        cp_commit();
    };

    load_chunk(0, 0);
    load_chunk(1, 1);
    for (int c = 0; c < nc; c++) {
        int s = c % 3;
        if (c + 1 < nc) cp_wait1(); else cp_wait0();
        __syncthreads();
        if (c + 2 < nc) load_chunk(c + 2, (c + 2) % 3);
        uint32_t sA = sbase + s * HG_STG;
        uint32_t sB = sA + 10240;
#pragma unroll
        for (int ks = 0; ks < 2; ks++) {
            uint32_t af[2][4];
            ldmat4(af[0][0], af[0][1], af[0][2], af[0][3],
                   sA + (uint32_t)(aRowOff) * 80 + ks * 32 + aByte);
            ldmat4(af[1][0], af[1][1], af[1][2], af[1][3],
                   sA + (uint32_t)(aRowOff + 16) * 80 + ks * 32 + aByte);
            uint32_t bfr[4][4];
#pragma unroll
            for (int bi = 0; bi < 4; bi++)
                ldmat4(bfr[bi][0], bfr[bi][1], bfr[bi][2], bfr[bi][3],
                       sB + (uint32_t)(bRowOff + bi * 16) * 80 + ks * 32 + bByte);
#pragma unroll
            for (int mi = 0; mi < 2; mi++)
#pragma unroll
                for (int ni = 0; ni < 8; ni++) {
                    int bi = ni >> 1, hb = (ni & 1) * 2;
                    mma16816(acc[mi][ni], af[mi], bfr[bi][hb], bfr[bi][hb + 1]);
                }
        }
    }
    __syncthreads();

    // stage accumulators into smem [128][132]
    float* sC = reinterpret_cast<float*>(smem);
    int g = lane >> 2, tg = lane & 3;
#pragma unroll
    for (int mi = 0; mi < 2; mi++)
#pragma unroll
        for (int ni = 0; ni < 8; ni++) {
            int r0 = wm0 + mi * 16 + g;
            int c0 = wn0 + ni * 8 + tg * 2;
            sC[r0 * 132 + c0]           = acc[mi][ni][0];
            sC[r0 * 132 + c0 + 1]       = acc[mi][ni][1];
            sC[(r0 + 8) * 132 + c0]     = acc[mi][ni][2];
            sC[(r0 + 8) * 132 + c0 + 1] = acc[mi][ni][3];
        }
    __syncthreads();

    // coalesced fused epilogue
    for (int i = tid; i < 16384; i += 256) {
        int row = i >> 7, col = i & 127;
        int gm = m0 + row, gn = n0 + col;
        float v = sC[row * 132 + col];
        if constexpr (EPI == TEPI_BIASP) {
            v += bias[gn];
            size_t oidx = (size_t)gm * ldo + gn;
            __nv_bfloat16 h = __float2bfloat16(v);
            outh[oidx] = h;
            outl[oidx] = __float2bfloat16(v - __bfloat162float(h));
        } else if constexpr (EPI == TEPI_SCORES) {
            size_t idx = (size_t)gm * ldc + gn;
            v = v * alpha + C[idx];
            if (maskp[(size_t)zb * 512 + gn] == 0) v = -1e30f;
            C[idx] = v;
        } else if constexpr (EPI == TEPI_GELUP) {
            v += bias[gn];
            float gl = 0.5f * v * (1.0f + erff(v * 0.70710678118654752f));
            size_t oidx = (size_t)gm * ldo + gn;
            __nv_bfloat16 h = __float2bfloat16(gl);
            outh[oidx] = h;
            outl[oidx] = __float2bfloat16(gl - __bfloat162float(h));
        } else {  // TEPI_RESGATE
            size_t idx = (size_t)gm * ldc + gn;
            v += bias[gn];
            float gt = gate[(gm >> 9) * 6144 + gn];
            C[idx] = res[idx] + gt * v;
        }
    }
}

// ---------------- HMMA bf16x3 PV (NN via ldmatrix.trans) ----------------
// per z=(b,h): O[512,64] = P[512,512] @ V[512,64]; writes ao bf16 pairs
static constexpr int PV_ASTG = 128 * 80;   // 10240
static constexpr int PV_BSTG = 32 * 144;   // 4608
static constexpr int PV_STG  = PV_ASTG + PV_BSTG;  // 14848
static constexpr int PV_SMEM = 3 * PV_STG; // 44544 >= epi 128*68*4=34816

__global__ __launch_bounds__(256) void hmma_pv(
    const __nv_bfloat16* __restrict__ ph, const __nv_bfloat16* __restrict__ pl,
    const __nv_bfloat16* __restrict__ vh, const __nv_bfloat16* __restrict__ vl,
    __nv_bfloat16* __restrict__ aoh, __nv_bfloat16* __restrict__ aol)
{
    extern __shared__ char smem[];
    uint32_t sbase = smem_u32(smem);
    int tid = threadIdx.x;
    int z = blockIdx.z;
    int zb = z >> 4, zh = z & 15;
    int m0 = blockIdx.y * 128;
    const __nv_bfloat16* Ah = ph + (size_t)z * 262144;
    const __nv_bfloat16* Al = pl + (size_t)z * 262144;
    const __nv_bfloat16* Bh = vh + (size_t)zb * 512 * 3072 + 2048 + zh * 64;
    const __nv_bfloat16* Bl = vl + (size_t)zb * 512 * 3072 + 2048 + zh * 64;

    int w = tid >> 5, lane = tid & 31;
    int wm0 = (w & 3) * 32;      // 4 warps along M
    int wn0 = (w >> 2) * 32;     // 2 warps along N
    int mm = lane >> 3, rr = lane & 7;
    int aRowOff = wm0 + ((mm & 1) << 3) + rr;
    int aByte   = (mm >> 1) << 4;

    float acc[2][4][4];
#pragma unroll
    for (int mi = 0; mi < 2; mi++)
#pragma unroll
        for (int ni = 0; ni < 4; ni++)
#pragma unroll
            for (int q = 0; q < 4; q++) acc[mi][ni][q] = 0.0f;

    const int nc = 48;  // 3*512/32

    auto load_chunk = [&](int c, int s) {
        int kk = c << 5;
        int blk = (kk >= 512) + (kk >= 1024);
        int koff = kk - blk * 512;
        const __nv_bfloat16* pA = (blk == 1) ? Al : Ah;
        const __nv_bfloat16* pB = (blk == 2) ? Bl : Bh;
        uint32_t sA = sbase + s * PV_STG;
        uint32_t sB = sA + PV_ASTG;
        // A: 128 rows x 64B (4 chunks/row) = 512 cp16
#pragma unroll
        for (int u = 0; u < 2; u++) {
            int j = u * 256 + tid;
            int r = j >> 2, ch = j & 3;
            cp16(sA + r * 80 + ch * 16, pA + (size_t)(m0 + r) * 512 + koff + ch * 8);
        }
        // B: 32 rows (k) x 128B (8 chunks/row) = 256 cp16
        {
            int r = tid >> 3, ch = tid & 7;
            cp16(sB + r * 144 + ch * 16, pB + (size_t)(koff + r) * 3072 + ch * 8);
        }
        cp_commit();
    };

    load_chunk(0, 0);
    load_chunk(1, 1);
    for (int c = 0; c < nc; c++) {
        int s = c % 3;
        if (c + 1 < nc) cp_wait1(); else cp_wait0();
        __syncthreads();
        if (c + 2 < nc) load_chunk(c + 2, (c + 2) % 3);
        uint32_t sA = sbase + s * PV_STG;
        uint32_t sB = sA + PV_ASTG;
#pragma unroll
        for (int ks = 0; ks < 2; ks++) {
            uint32_t af[2][4];
            ldmat4(af[0][0], af[0][1], af[0][2], af[0][3],
                   sA + (uint32_t)(aRowOff) * 80 + ks * 32 + aByte);
            ldmat4(af[1][0], af[1][1], af[1][2], af[1][3],
                   sA + (uint32_t)(aRowOff + 16) * 80 + ks * 32 + aByte);
            // B via trans: matrices {k0n0, k8n0, k0n8, k8n8} per ldmat4t
            uint32_t bt[2][4];
#pragma unroll
            for (int nh = 0; nh < 2; nh++) {
                uint32_t addr = sB
                    + (uint32_t)(ks * 16 + (((lane >> 3) & 1) << 3) + (lane & 7)) * 144
                    + (uint32_t)(wn0 + nh * 16 + ((lane >> 4) << 3)) * 2;
                ldmat4t(bt[nh][0], bt[nh][1], bt[nh][2], bt[nh][3], addr);
            }
#pragma unroll
            for (int mi = 0; mi < 2; mi++)
#pragma unroll
                for (int ni = 0; ni < 4; ni++) {
                    int nh = ni >> 1, ng = ni & 1;
                    mma16816(acc[mi][ni], af[mi], bt[nh][2 * ng], bt[nh][2 * ng + 1]);
                }
        }
    }
    __syncthreads();

    // stage into smem [128][68]
    float* sC = reinterpret_cast<float*>(smem);
    int g = lane >> 2, tg = lane & 3;
#pragma unroll
    for (int mi = 0; mi < 2; mi++)
#pragma unroll
        for (int ni = 0; ni < 4; ni++) {
            int r0 = wm0 + mi * 16 + g;
            int c0 = wn0 + ni * 8 + tg * 2;
            sC[r0 * 68 + c0]           = acc[mi][ni][0];
            sC[r0 * 68 + c0 + 1]       = acc[mi][ni][1];
            sC[(r0 + 8) * 68 + c0]     = acc[mi][ni][2];
            sC[(r0 + 8) * 68 + c0 + 1] = acc[mi][ni][3];
        }
    __syncthreads();

    for (int i = tid; i < 8192; i += 256) {
        int row = i >> 6, col = i & 63;
        float v = sC[row * 68 + col];
        size_t oidx = (size_t)(zb * 512 + m0 + row) * 1024 + zh * 64 + col;
        __nv_bfloat16 h = __float2bfloat16(v);
        aoh[oidx] = h;
        aol[oidx] = __float2bfloat16(v - __bfloat162float(h));
    }
}

// ---------------- launcher ----------------
extern "C" void kernel_launch(void* const* d_in, const int* in_sizes, int n_in,
                              void* d_out, int out_size)
{
    const float* x      = (const float*)d_in[0];
    const float* t_emb  = (const float*)d_in[1];
    const float* rel    = (const float*)d_in[2];
    const int*   amask  = (const int*)d_in[3];
    const float* w_ada  = (const float*)d_in[4];
    const float* b_ada  = (const float*)d_in[5];
    const float* g1     = (const float*)d_in[6];
    const float* be1    = (const float*)d_in[7];
    const float* g2     = (const float*)d_in[8];
    const float* be2    = (const float*)d_in[9];
    const float* w_qkv  = (const float*)d_in[10];
    const float* b_qkv  = (const float*)d_in[11];
    const float* w_proj = (const float*)d_in[12];
    const float* b_proj = (const float*)d_in[13];
    const float* w_rp1  = (const float*)d_in[14];
    const float* b_rp1  = (const float*)d_in[15];
    const float* w_rp2  = (const float*)d_in[16];
    const float* b_rp2  = (const float*)d_in[17];
    const float* w_fc1  = (const float*)d_in[18];
    const float* b_fc1  = (const float*)d_in[19];
    const float* w_fc2  = (const float*)d_in[20];
    const float* b_fc2  = (const float*)d_in[21];
    float* out = (float*)d_out;

    float *mod, *att, *x1;
    __nv_bfloat16 *xnh, *xnl, *qph, *qpl, *pph, *ppl, *aoh, *aol, *hh, *hl;
    __nv_bfloat16 *wqkvh, *wqkvl, *wprojh, *wprojl, *wfc1h, *wfc1l, *wfc2h, *wfc2l;
    cudaGetSymbolAddress((void**)&mod, g_mod);
    cudaGetSymbolAddress((void**)&att, g_att);
    cudaGetSymbolAddress((void**)&x1,  g_x1);
    cudaGetSymbolAddress((void**)&xnh, g_xnh);
    cudaGetSymbolAddress((void**)&xnl, g_xnl);
    cudaGetSymbolAddress((void**)&qph, g_qkvph);
    cudaGetSymbolAddress((void**)&qpl, g_qkvpl);
    cudaGetSymbolAddress((void**)&pph, g_ph);
    cudaGetSymbolAddress((void**)&ppl, g_pl);
    cudaGetSymbolAddress((void**)&aoh, g_aoh);
    cudaGetSymbolAddress((void**)&aol, g_aol);
    cudaGetSymbolAddress((void**)&hh,  g_hh);
    cudaGetSymbolAddress((void**)&hl,  g_hl);
    cudaGetSymbolAddress((void**)&wqkvh, g_wqkvh);
    cudaGetSymbolAddress((void**)&wqkvl, g_wqkvl);
    cudaGetSymbolAddress((void**)&wprojh, g_wprojh);
    cudaGetSymbolAddress((void**)&wprojl, g_wprojl);
    cudaGetSymbolAddress((void**)&wfc1h, g_wfc1h);
    cudaGetSymbolAddress((void**)&wfc1l, g_wfc1l);
    cudaGetSymbolAddress((void**)&wfc2h, g_wfc2h);
    cudaGetSymbolAddress((void**)&wfc2l, g_wfc2l);

    cudaFuncSetAttribute(hmma_gemm<TEPI_BIASP>,   cudaFuncAttributeMaxDynamicSharedMemorySize, HG_SMEM);
    cudaFuncSetAttribute(hmma_gemm<TEPI_SCORES>,  cudaFuncAttributeMaxDynamicSharedMemorySize, HG_SMEM);
    cudaFuncSetAttribute(hmma_gemm<TEPI_GELUP>,   cudaFuncAttributeMaxDynamicSharedMemorySize, HG_SMEM);
    cudaFuncSetAttribute(hmma_gemm<TEPI_RESGATE>, cudaFuncAttributeMaxDynamicSharedMemorySize, HG_SMEM);
    cudaFuncSetAttribute(hmma_pv,                 cudaFuncAttributeMaxDynamicSharedMemorySize, PV_SMEM);

    // weight splits
    split_kernel<<<3072, 256>>>(w_qkv,  wqkvh,  wqkvl,  3072 * 1024 / 4);
    split_kernel<<<1024, 256>>>(w_proj, wprojh, wprojl, 1024 * 1024 / 4);
    split_kernel<<<4096, 256>>>(w_fc1,  wfc1h,  wfc1l,  4096 * 1024 / 4);
    split_kernel<<<4096, 256>>>(w_fc2,  wfc2h,  wfc2l,  4096 * 1024 / 4);

    // 1. adaLN modulation
    ada_kernel<<<768, 256>>>(t_emb, w_ada, b_ada, mod);
    // 2. LN1 + modulate
    ln_mod_kernel<<<2048, 256>>>(x, g1, be1, mod, 0, 1, xnh, xnl);
    // 3. qkv -> bf16 pairs
    hmma_gemm<TEPI_BIASP><<<dim3(24, 16, 1), 256, HG_SMEM>>>(
        xnh, xnl, 1024, wqkvh, wqkvl, 1024, nullptr, 0, 1024, 1,
        0, 0, 0, 0, 0, 0, b_qkv, nullptr, nullptr, nullptr, 0.f, qph, qpl, 3072);
    // 4. rel-pos bias
    relpos_kernel<<<4096, 256>>>(rel, w_rp1, b_rp1, w_rp2, b_rp2, att);
    // 5. scores (HMMA, batched over b,h)
    hmma_gemm<TEPI_SCORES><<<dim3(4, 4, 64), 256, HG_SMEM>>>(
        qph, qpl, 3072, qph + 1024, qpl + 1024, 3072, att, 512, 64, 16,
        512LL * 3072, 64, 512LL * 3072, 64, 1LL << 22, 1LL << 18,
        nullptr, nullptr, nullptr, amask, 0.125f, nullptr, nullptr, 0);
    // 6. softmax -> bf16 pair P
    softmax_kernel<<<4096, 256>>>(att, pph, ppl);
    // 7. O = P @ V (HMMA NN) -> ao pairs
    hmma_pv<<<dim3(1, 4, 64), 256, PV_SMEM>>>(pph, ppl, qph, qpl, aoh, aol);
    // 8. proj + gated residual
    hmma_gemm<TEPI_RESGATE><<<dim3(8, 16, 1), 256, HG_SMEM>>>(
        aoh, aol, 1024, wprojh, wprojl, 1024, x1, 1024, 1024, 1,
        0, 0, 0, 0, 0, 0, b_proj, x, mod + 2048, nullptr, 0.f, nullptr, nullptr, 0);
    // 9. LN2 + modulate
    ln_mod_kernel<<<2048, 256>>>(x1, g2, be2, mod, 3, 4, xnh, xnl);
    // 10. fc1 + gelu -> pairs
    hmma_gemm<TEPI_GELUP><<<dim3(32, 16, 1), 256, HG_SMEM>>>(
        xnh, xnl, 1024, wfc1h, wfc1l, 1024, nullptr, 0, 1024, 1,
        0, 0, 0, 0, 0, 0, b_fc1, nullptr, nullptr, nullptr, 0.f, hh, hl, 4096);
    // 11. fc2 + gated residual -> out
    hmma_gemm<TEPI_RESGATE><<<dim3(8, 16, 1), 256, HG_SMEM>>>(
        hh, hl, 4096, wfc2h, wfc2l, 4096, out, 1024, 4096, 1,
        0, 0, 0, 0, 0, 0, b_fc2, x1, mod + 5120, nullptr, 0.f, nullptr, nullptr, 0);
}

// round 10
// speedup vs baseline: 1.0811x; 1.0811x over previous
#include <cuda_runtime.h>
#include <cuda_bf16.h>
#include <math.h>
#include <stdint.h>

// B=4, N=512, D=1024, H=16, HD=64, HID=4096, RP_HID=64; tokens M=2048

#define TEPI_BIASP   0
#define TEPI_GELUP   1
#define TEPI_RESGATE 2

// ---------------- scratch ----------------
__device__ float g_mod[4 * 6144];
__device__ float g_att[4 * 16 * 512 * 512];
__device__ float g_x1[2048 * 1024];
__device__ __nv_bfloat16 g_xnh[2048 * 1024], g_xnl[2048 * 1024];
__device__ __nv_bfloat16 g_qkvph[2048 * 3072], g_qkvpl[2048 * 3072];
__device__ __nv_bfloat16 g_aoh[2048 * 1024], g_aol[2048 * 1024];
__device__ __nv_bfloat16 g_hh[2048 * 4096], g_hl[2048 * 4096];
__device__ __nv_bfloat16 g_wqkvh[3072 * 1024], g_wqkvl[3072 * 1024];
__device__ __nv_bfloat16 g_wprojh[1024 * 1024], g_wprojl[1024 * 1024];
__device__ __nv_bfloat16 g_wfc1h[4096 * 1024], g_wfc1l[4096 * 1024];
__device__ __nv_bfloat16 g_wfc2h[1024 * 4096], g_wfc2l[1024 * 4096];

// ---------------- helpers ----------------
__device__ __forceinline__ uint32_t smem_u32(const void* p) {
    uint32_t a;
    asm("{ .reg .u64 t; cvta.to.shared.u64 t, %1; cvt.u32.u64 %0, t; }" : "=r"(a) : "l"(p));
    return a;
}
__device__ __forceinline__ void cp16(uint32_t s, const void* g) {
    asm volatile("cp.async.cg.shared.global [%0], [%1], 16;" :: "r"(s), "l"(g));
}
__device__ __forceinline__ void cp_commit() {
    asm volatile("cp.async.commit_group;" ::: "memory");
}
__device__ __forceinline__ void cp_wait0() {
    asm volatile("cp.async.wait_group 0;" ::: "memory");
}
__device__ __forceinline__ void cp_wait1() {
    asm volatile("cp.async.wait_group 1;" ::: "memory");
}
__device__ __forceinline__ void ldmat4(uint32_t& r0, uint32_t& r1, uint32_t& r2, uint32_t& r3, uint32_t a) {
    asm volatile("ldmatrix.sync.aligned.m8n8.x4.shared.b16 {%0,%1,%2,%3}, [%4];"
                 : "=r"(r0), "=r"(r1), "=r"(r2), "=r"(r3) : "r"(a));
}
__device__ __forceinline__ void ldmat4t(uint32_t& r0, uint32_t& r1, uint32_t& r2, uint32_t& r3, uint32_t a) {
    asm volatile("ldmatrix.sync.aligned.m8n8.x4.trans.shared.b16 {%0,%1,%2,%3}, [%4];"
                 : "=r"(r0), "=r"(r1), "=r"(r2), "=r"(r3) : "r"(a));
}
__device__ __forceinline__ void mma16816(float* c, const uint32_t* a, uint32_t b0, uint32_t b1) {
    asm volatile(
        "mma.sync.aligned.m16n8k16.row.col.f32.bf16.bf16.f32 "
        "{%0,%1,%2,%3}, {%4,%5,%6,%7}, {%8,%9}, {%0,%1,%2,%3};"
        : "+f"(c[0]), "+f"(c[1]), "+f"(c[2]), "+f"(c[3])
        : "r"(a[0]), "r"(a[1]), "r"(a[2]), "r"(a[3]), "r"(b0), "r"(b1));
}
__device__ __forceinline__ uint32_t packbf2(float a, float b) {
    __nv_bfloat162 h = __float22bfloat162_rn(make_float2(a, b));
    return *reinterpret_cast<uint32_t*>(&h);
}

// ---------------- adaLN ----------------
__global__ __launch_bounds__(256) void ada_kernel(
    const float* __restrict__ t_emb, const float* __restrict__ w_ada,
    const float* __restrict__ b_ada, float* __restrict__ mod)
{
    __shared__ float sh[4096];
    int tid = threadIdx.x;
    for (int i = tid; i < 4096; i += 256) {
        float t = t_emb[i];
        sh[i] = t / (1.0f + __expf(-t));
    }
    __syncthreads();
    int j = blockIdx.x * 8 + (tid >> 5);
    int lane = tid & 31;
    const float* wr = w_ada + (size_t)j * 1024;
    float a0 = 0.f, a1 = 0.f, a2 = 0.f, a3 = 0.f;
    for (int k = lane; k < 1024; k += 32) {
        float w = wr[k];
        a0 = fmaf(w, sh[k], a0);
        a1 = fmaf(w, sh[1024 + k], a1);
        a2 = fmaf(w, sh[2048 + k], a2);
        a3 = fmaf(w, sh[3072 + k], a3);
    }
    for (int o = 16; o; o >>= 1) {
        a0 += __shfl_xor_sync(0xffffffffu, a0, o);
        a1 += __shfl_xor_sync(0xffffffffu, a1, o);
        a2 += __shfl_xor_sync(0xffffffffu, a2, o);
        a3 += __shfl_xor_sync(0xffffffffu, a3, o);
    }
    if (lane == 0) {
        float bb = b_ada[j];
        mod[j]            = a0 + bb;
        mod[6144 + j]     = a1 + bb;
        mod[2 * 6144 + j] = a2 + bb;
        mod[3 * 6144 + j] = a3 + bb;
    }
}

// ---------------- LN + modulation -> bf16 pair ----------------
__global__ __launch_bounds__(256) void ln_mod_kernel(
    const float* __restrict__ xin, const float* __restrict__ gamma,
    const float* __restrict__ beta, const float* __restrict__ mod,
    int shift_chunk, int scale_chunk,
    __nv_bfloat16* __restrict__ outh, __nv_bfloat16* __restrict__ outl)
{
    int token = blockIdx.x;
    int b = token >> 9;
    int tid = threadIdx.x;
    const float* xr = xin + (size_t)token * 1024;
    float v[4];
    float s = 0.f, sq = 0.f;
#pragma unroll
    for (int i = 0; i < 4; i++) {
        float t = xr[i * 256 + tid];
        v[i] = t; s += t; sq += t * t;
    }
    for (int o = 16; o; o >>= 1) {
        s  += __shfl_xor_sync(0xffffffffu, s, o);
        sq += __shfl_xor_sync(0xffffffffu, sq, o);
    }
    __shared__ float ss[8], ssq[8], smu, srstd;
    int wid = tid >> 5, lane = tid & 31;
    if (lane == 0) { ss[wid] = s; ssq[wid] = sq; }
    __syncthreads();
    if (tid == 0) {
        float S = 0.f, Q = 0.f;
        for (int i = 0; i < 8; i++) { S += ss[i]; Q += ssq[i]; }
        float mu = S * (1.0f / 1024.0f);
        float var = Q * (1.0f / 1024.0f) - mu * mu;
        smu = mu; srstd = rsqrtf(var + 1e-5f);
    }
    __syncthreads();
    float mu = smu, rstd = srstd;
    const float* modb = mod + (size_t)b * 6144;
    const float* shm = modb + shift_chunk * 1024;
    const float* scm = modb + scale_chunk * 1024;
    size_t rb = (size_t)token * 1024;
#pragma unroll
    for (int i = 0; i < 4; i++) {
        int c = i * 256 + tid;
        float ln = (v[i] - mu) * rstd * gamma[c] + beta[c];
        float o = ln * (1.0f + scm[c]) + shm[c];
        __nv_bfloat16 h = __float2bfloat16(o);
        outh[rb + c] = h;
        outl[rb + c] = __float2bfloat16(o - __bfloat162float(h));
    }
}

// ---------------- split fp32 -> bf16 pair (weights) ----------------
__global__ __launch_bounds__(256) void split_kernel(
    const float* __restrict__ src, __nv_bfloat16* __restrict__ hi,
    __nv_bfloat16* __restrict__ lo, int n4)
{
    int i = blockIdx.x * 256 + threadIdx.x;
    if (i >= n4) return;
    float4 v = reinterpret_cast<const float4*>(src)[i];
    __nv_bfloat16 h0 = __float2bfloat16(v.x), h1 = __float2bfloat16(v.y);
    __nv_bfloat16 h2 = __float2bfloat16(v.z), h3 = __float2bfloat16(v.w);
    __nv_bfloat162 H0; H0.x = h0; H0.y = h1;
    __nv_bfloat162 H1; H1.x = h2; H1.y = h3;
    __nv_bfloat162 L0, L1;
    L0.x = __float2bfloat16(v.x - __bfloat162float(h0));
    L0.y = __float2bfloat16(v.y - __bfloat162float(h1));
    L1.x = __float2bfloat16(v.z - __bfloat162float(h2));
    L1.y = __float2bfloat16(v.w - __bfloat162float(h3));
    reinterpret_cast<__nv_bfloat162*>(hi)[2 * i]     = H0;
    reinterpret_cast<__nv_bfloat162*>(hi)[2 * i + 1] = H1;
    reinterpret_cast<__nv_bfloat162*>(lo)[2 * i]     = L0;
    reinterpret_cast<__nv_bfloat162*>(lo)[2 * i + 1] = L1;
}

// ---------------- rel-pos bias MLP ----------------
__global__ __launch_bounds__(256) void relpos_kernel(
    const float* __restrict__ rel, const float* __restrict__ w1,
    const float* __restrict__ b1, const float* __restrict__ w2,
    const float* __restrict__ b2, float* __restrict__ out)
{
    __shared__ float sw1[128], sb1[64], sw2[1024], sb2[16];
    int tid = threadIdx.x;
    if (tid < 128) sw1[tid] = w1[tid];
    if (tid < 64)  sb1[tid] = b1[tid];
    for (int i = tid; i < 1024; i += 256) sw2[i] = w2[i];
    if (tid < 16)  sb2[tid] = b2[tid];
    __syncthreads();
    int gid = blockIdx.x * 256 + tid;
    float r0 = rel[2 * (size_t)gid];
    float r1 = rel[2 * (size_t)gid + 1];
    float h[64];
#pragma unroll
    for (int u = 0; u < 64; u++)
        h[u] = fmaxf(fmaf(sw1[2 * u], r0, fmaf(sw1[2 * u + 1], r1, sb1[u])), 0.0f);
    int b = gid >> 18;
    int rem = gid & 262143;
    size_t base = ((size_t)b << 22) + (size_t)rem;
#pragma unroll
    for (int hh = 0; hh < 16; hh++) {
        float s2 = sb2[hh];
#pragma unroll
        for (int u = 0; u < 64; u++)
            s2 = fmaf(h[u], sw2[hh * 64 + u], s2);
        out[base + ((size_t)hh << 18)] = s2;
    }
}

// ---------------- HMMA bf16x3 GEMM (NT): C = A[M,K] @ B[N,K]^T ----------------
static constexpr int HG_STG  = 20480;
static constexpr int HG_SMEM = 128 * 132 * 4;    // 67584 >= 3*20480

template<int EPI>
__global__ __launch_bounds__(256) void hmma_gemm(
    const __nv_bfloat16* __restrict__ Ah, const __nv_bfloat16* __restrict__ Al, int lda,
    const __nv_bfloat16* __restrict__ Bh, const __nv_bfloat16* __restrict__ Bl, int ldb,
    float* __restrict__ C, int ldc, int K,
    const float* __restrict__ bias, const float* __restrict__ res,
    const float* __restrict__ gate,
    __nv_bfloat16* __restrict__ outh, __nv_bfloat16* __restrict__ outl, int ldo)
{
    extern __shared__ char smem[];
    uint32_t sbase = smem_u32(smem);
    int tid = threadIdx.x;
    int m0 = blockIdx.y * 128;
    int n0 = blockIdx.x * 128;

    int w = tid >> 5;
    int lane = tid & 31;
    int wm0 = (w & 3) * 32;
    int wn0 = (w >> 2) * 64;
    int mm = lane >> 3, rr = lane & 7;
    int aRowOff = wm0 + ((mm & 1) << 3) + rr;
    int aByte   = (mm >> 1) << 4;
    int bRowOff = wn0 + ((mm >> 1) << 3) + rr;
    int bByte   = (mm & 1) << 4;

    float acc[2][8][4];
#pragma unroll
    for (int mi = 0; mi < 2; mi++)
#pragma unroll
        for (int ni = 0; ni < 8; ni++)
#pragma unroll
            for (int q = 0; q < 4; q++) acc[mi][ni][q] = 0.0f;

    int nc = (3 * K) >> 5;

    auto load_chunk = [&](int c, int s) {
        int kk = c << 5;
        int blk = (kk >= K) + (kk >= 2 * K);
        int koff = kk - blk * K;
        const __nv_bfloat16* pA = (blk == 1) ? Al : Ah;
        const __nv_bfloat16* pB = (blk == 2) ? Bl : Bh;
        uint32_t sA = sbase + s * HG_STG;
        uint32_t sB = sA + 10240;
#pragma unroll
        for (int u = 0; u < 2; u++) {
            int i = u * 256 + tid;
            int ch = i >> 7, r = i & 127;
            cp16(sA + r * 80 + ch * 16, pA + (size_t)(m0 + r) * lda + koff + ch * 8);
            cp16(sB + r * 80 + ch * 16, pB + (size_t)(n0 + r) * ldb + koff + ch * 8);
        }
        cp_commit();
    };

    load_chunk(0, 0);
    load_chunk(1, 1);
    for (int c = 0; c < nc; c++) {
        int s = c % 3;
        if (c + 1 < nc) cp_wait1(); else cp_wait0();
        __syncthreads();
        if (c + 2 < nc) load_chunk(c + 2, (c + 2) % 3);
        uint32_t sA = sbase + s * HG_STG;
        uint32_t sB = sA + 10240;
#pragma unroll
        for (int ks = 0; ks < 2; ks++) {
            uint32_t af[2][4];
            ldmat4(af[0][0], af[0][1], af[0][2], af[0][3],
                   sA + (uint32_t)(aRowOff) * 80 + ks * 32 + aByte);
            ldmat4(af[1][0], af[1][1], af[1][2], af[1][3],
                   sA + (uint32_t)(aRowOff + 16) * 80 + ks * 32 + aByte);
            uint32_t bfr[4][4];
#pragma unroll
            for (int bi = 0; bi < 4; bi++)
                ldmat4(bfr[bi][0], bfr[bi][1], bfr[bi][2], bfr[bi][3],
                       sB + (uint32_t)(bRowOff + bi * 16) * 80 + ks * 32 + bByte);
#pragma unroll
            for (int mi = 0; mi < 2; mi++)
#pragma unroll
                for (int ni = 0; ni < 8; ni++) {
                    int bi = ni >> 1, hb = (ni & 1) * 2;
                    mma16816(acc[mi][ni], af[mi], bfr[bi][hb], bfr[bi][hb + 1]);
                }
        }
    }
    __syncthreads();

    float* sC = reinterpret_cast<float*>(smem);
    int g = lane >> 2, tg = lane & 3;
#pragma unroll
    for (int mi = 0; mi < 2; mi++)
#pragma unroll
        for (int ni = 0; ni < 8; ni++) {
            int r0 = wm0 + mi * 16 + g;
            int c0 = wn0 + ni * 8 + tg * 2;
            sC[r0 * 132 + c0]           = acc[mi][ni][0];
            sC[r0 * 132 + c0 + 1]       = acc[mi][ni][1];
            sC[(r0 + 8) * 132 + c0]     = acc[mi][ni][2];
            sC[(r0 + 8) * 132 + c0 + 1] = acc[mi][ni][3];
        }
    __syncthreads();

    for (int i = tid; i < 16384; i += 256) {
        int row = i >> 7, col = i & 127;
        int gm = m0 + row, gn = n0 + col;
        float v = sC[row * 132 + col];
        if constexpr (EPI == TEPI_BIASP) {
            v += bias[gn];
            size_t oidx = (size_t)gm * ldo + gn;
            __nv_bfloat16 h = __float2bfloat16(v);
            outh[oidx] = h;
            outl[oidx] = __float2bfloat16(v - __bfloat162float(h));
        } else if constexpr (EPI == TEPI_GELUP) {
            v += bias[gn];
            float gl = 0.5f * v * (1.0f + erff(v * 0.70710678118654752f));
            size_t oidx = (size_t)gm * ldo + gn;
            __nv_bfloat16 h = __float2bfloat16(gl);
            outh[oidx] = h;
            outl[oidx] = __float2bfloat16(gl - __bfloat162float(h));
        } else {  // TEPI_RESGATE
            size_t idx = (size_t)gm * ldc + gn;
            v += bias[gn];
            float gt = gate[(gm >> 9) * 6144 + gn];
            C[idx] = res[idx] + gt * v;
        }
    }
}

// ---------------- fused flash attention (bf16x3 QK^T + online softmax + bf16x3 PV) ----------------
// CTA: z=(b,h) x 128 q-rows. 8 warps, each owns 16 q-rows. Key loop: 8 blocks of 64.
// smem: Qh/Ql 128x144 each; 3 stages of (Kh,Kl,Vh,Vl) 64x144 each.
static constexpr int FA_Q    = 2 * 128 * 144;       // 36864
static constexpr int FA_KV   = 4 * 64 * 144;        // 36864 per stage
static constexpr int FA_SMEM = FA_Q + 3 * FA_KV;    // 147456

__global__ __launch_bounds__(256) void fused_attn(
    const __nv_bfloat16* __restrict__ qph, const __nv_bfloat16* __restrict__ qpl,
    const float* __restrict__ att, const int* __restrict__ amask,
    __nv_bfloat16* __restrict__ aoh, __nv_bfloat16* __restrict__ aol)
{
    extern __shared__ char smem[];
    uint32_t sbase = smem_u32(smem);
    int tid = threadIdx.x;
    int z = blockIdx.x, zb = z >> 4, zh = z & 15;
    int qb = blockIdx.y;
    int w = tid >> 5, lane = tid & 31;
    int g = lane >> 2, tg = lane & 3;
    int mm = lane >> 3, rr = lane & 7;
    size_t tokq = (size_t)(zb * 512 + qb * 128);

    auto load_q = [&]() {
#pragma unroll
        for (int t = 0; t < 8; t++) {
            int idx = t * 256 + tid;
            int arr = idx >> 10;
            int rem = idx & 1023;
            int r = rem >> 3, ch = rem & 7;
            const __nv_bfloat16* src = (arr ? qpl : qph) + (tokq + r) * 3072 + zh * 64 + ch * 8;
            cp16(sbase + arr * 18432 + (uint32_t)r * 144 + ch * 16, src);
        }
    };
    auto load_kv = [&](int j, int s) {
        uint32_t base = sbase + FA_Q + s * FA_KV;
        size_t tokk = (size_t)(zb * 512 + j * 64);
#pragma unroll
        for (int t = 0; t < 8; t++) {
            int idx = t * 256 + tid;
            int arr = idx >> 9;               // 0 Kh,1 Kl,2 Vh,3 Vl
            int rem = idx & 511;
            int r = rem >> 3, ch = rem & 7;
            const __nv_bfloat16* p = (arr & 1) ? qpl : qph;
            int off = (arr < 2) ? 1024 : 2048;
            cp16(base + arr * 9216 + (uint32_t)r * 144 + ch * 16,
                 p + (tokk + r) * 3072 + off + zh * 64 + ch * 8);
        }
        cp_commit();
    };

    load_q();
    load_kv(0, 0);   // group0 = Q + KV0
    load_kv(1, 1);   // group1

    uint32_t qfh[4][4], qfl[4][4];
    float Oacc[8][4];
#pragma unroll
    for (int nf = 0; nf < 8; nf++)
#pragma unroll
        for (int q = 0; q < 4; q++) Oacc[nf][q] = 0.0f;
    float m0 = -1e30f, m1 = -1e30f, l0 = 0.0f, l1 = 0.0f;

    int qrow0 = qb * 128 + w * 16 + g;
    const float* bb0 = att + ((size_t)z << 18) + (size_t)qrow0 * 512;
    const float* bb1 = bb0 + 8 * 512;
    const int* mbase = amask + zb * 512;

    bool qloaded = false;
    for (int j = 0; j < 8; j++) {
        int s = j % 3;
        if (j + 1 < 8) cp_wait1(); else cp_wait0();
        __syncthreads();
        if (j + 2 < 8) load_kv(j + 2, (j + 2) % 3);

        if (!qloaded) {
            uint32_t arow = (uint32_t)(w * 16 + ((mm & 1) << 3) + rr) * 144 + ((mm >> 1) << 4);
#pragma unroll
            for (int ks = 0; ks < 4; ks++) {
                ldmat4(qfh[ks][0], qfh[ks][1], qfh[ks][2], qfh[ks][3], sbase + arow + ks * 32);
                ldmat4(qfl[ks][0], qfl[ks][1], qfl[ks][2], qfl[ks][3], sbase + 18432 + arow + ks * 32);
            }
            qloaded = true;
        }

        uint32_t kh = sbase + FA_Q + s * FA_KV;
        uint32_t kl = kh + 9216;
        uint32_t vh = kh + 18432;
        uint32_t vl = kh + 27648;

        // ---- scores: S = Q.K^T (bf16x3) ----
        float Sacc[8][4];
#pragma unroll
        for (int nf = 0; nf < 8; nf++)
#pragma unroll
            for (int q = 0; q < 4; q++) Sacc[nf][q] = 0.0f;
        uint32_t brow = (uint32_t)(((mm >> 1) << 3) + rr) * 144 + ((mm & 1) << 4);
#pragma unroll
        for (int ks = 0; ks < 4; ks++) {
            uint32_t bh[4][4], bl2[4][4];
#pragma unroll
            for (int kb = 0; kb < 4; kb++) {
                uint32_t o = brow + (uint32_t)kb * (16 * 144) + ks * 32;
                ldmat4(bh[kb][0], bh[kb][1], bh[kb][2], bh[kb][3], kh + o);
                ldmat4(bl2[kb][0], bl2[kb][1], bl2[kb][2], bl2[kb][3], kl + o);
            }
#pragma unroll
            for (int nf = 0; nf < 8; nf++) {
                int kb = nf >> 1, hb = (nf & 1) * 2;
                mma16816(Sacc[nf], qfh[ks], bh[kb][hb], bh[kb][hb + 1]);
                mma16816(Sacc[nf], qfl[ks], bh[kb][hb], bh[kb][hb + 1]);
                mma16816(Sacc[nf], qfh[ks], bl2[kb][hb], bl2[kb][hb + 1]);
            }
        }

        // ---- scale + bias + mask ----
        const float* br0 = bb0 + j * 64;
        const float* br1 = bb1 + j * 64;
        const int* mr = mbase + j * 64;
#pragma unroll
        for (int nf = 0; nf < 8; nf++) {
            int c0 = nf * 8 + tg * 2;
            float2 b0 = *reinterpret_cast<const float2*>(br0 + c0);
            float2 b1 = *reinterpret_cast<const float2*>(br1 + c0);
            int2 mv = *reinterpret_cast<const int2*>(mr + c0);
            Sacc[nf][0] = mv.x ? fmaf(Sacc[nf][0], 0.125f, b0.x) : -1e30f;
            Sacc[nf][1] = mv.y ? fmaf(Sacc[nf][1], 0.125f, b0.y) : -1e30f;
            Sacc[nf][2] = mv.x ? fmaf(Sacc[nf][2], 0.125f, b1.x) : -1e30f;
            Sacc[nf][3] = mv.y ? fmaf(Sacc[nf][3], 0.125f, b1.y) : -1e30f;
        }

        // ---- online softmax ----
        float mx0 = -1e30f, mx1 = -1e30f;
#pragma unroll
        for (int nf = 0; nf < 8; nf++) {
            mx0 = fmaxf(mx0, fmaxf(Sacc[nf][0], Sacc[nf][1]));
            mx1 = fmaxf(mx1, fmaxf(Sacc[nf][2], Sacc[nf][3]));
        }
        mx0 = fmaxf(mx0, __shfl_xor_sync(0xffffffffu, mx0, 1));
        mx0 = fmaxf(mx0, __shfl_xor_sync(0xffffffffu, mx0, 2));
        mx1 = fmaxf(mx1, __shfl_xor_sync(0xffffffffu, mx1, 1));
        mx1 = fmaxf(mx1, __shfl_xor_sync(0xffffffffu, mx1, 2));
        float mn0 = fmaxf(m0, mx0), mn1 = fmaxf(m1, mx1);
        float sc0 = __expf(m0 - mn0), sc1 = __expf(m1 - mn1);
        float rs0 = 0.0f, rs1 = 0.0f;
#pragma unroll
        for (int nf = 0; nf < 8; nf++) {
            Sacc[nf][0] = __expf(Sacc[nf][0] - mn0);
            Sacc[nf][1] = __expf(Sacc[nf][1] - mn0);
            Sacc[nf][2] = __expf(Sacc[nf][2] - mn1);
            Sacc[nf][3] = __expf(Sacc[nf][3] - mn1);
            rs0 += Sacc[nf][0] + Sacc[nf][1];
            rs1 += Sacc[nf][2] + Sacc[nf][3];
        }
        rs0 += __shfl_xor_sync(0xffffffffu, rs0, 1);
        rs0 += __shfl_xor_sync(0xffffffffu, rs0, 2);
        rs1 += __shfl_xor_sync(0xffffffffu, rs1, 1);
        rs1 += __shfl_xor_sync(0xffffffffu, rs1, 2);
        l0 = l0 * sc0 + rs0;
        l1 = l1 * sc1 + rs1;
        m0 = mn0; m1 = mn1;
#pragma unroll
        for (int nf = 0; nf < 8; nf++) {
            Oacc[nf][0] *= sc0; Oacc[nf][1] *= sc0;
            Oacc[nf][2] *= sc1; Oacc[nf][3] *= sc1;
        }

        // ---- PV: O += P.V (bf16x3), P from S accs ----
        uint32_t vrow = (uint32_t)((((lane >> 3) & 1) << 3) + (lane & 7)) * 144
                      + (uint32_t)((lane >> 4) << 3) * 2;
#pragma unroll
        for (int kk = 0; kk < 4; kk++) {
            // A-frags from Sacc (frags 2kk, 2kk+1)
            uint32_t aPh[4], aPl[4];
            {
                float* f0 = Sacc[2 * kk];
                float* f1 = Sacc[2 * kk + 1];
                aPh[0] = packbf2(f0[0], f0[1]);
                aPh[1] = packbf2(f0[2], f0[3]);
                aPh[2] = packbf2(f1[0], f1[1]);
                aPh[3] = packbf2(f1[2], f1[3]);
                __nv_bfloat162 h0 = *reinterpret_cast<__nv_bfloat162*>(&aPh[0]);
                __nv_bfloat162 h1 = *reinterpret_cast<__nv_bfloat162*>(&aPh[1]);
                __nv_bfloat162 h2 = *reinterpret_cast<__nv_bfloat162*>(&aPh[2]);
                __nv_bfloat162 h3 = *reinterpret_cast<__nv_bfloat162*>(&aPh[3]);
                aPl[0] = packbf2(f0[0] - __bfloat162float(h0.x), f0[1] - __bfloat162float(h0.y));
                aPl[1] = packbf2(f0[2] - __bfloat162float(h1.x), f0[3] - __bfloat162float(h1.y));
                aPl[2] = packbf2(f1[0] - __bfloat162float(h2.x), f1[1] - __bfloat162float(h2.y));
                aPl[3] = packbf2(f1[2] - __bfloat162float(h3.x), f1[3] - __bfloat162float(h3.y));
            }
            uint32_t vhf[4][4], vlf[4][4];
#pragma unroll
            for (int nh = 0; nh < 4; nh++) {
                uint32_t o = (uint32_t)(kk * 16) * 144 + vrow + (uint32_t)(nh * 16) * 2;
                ldmat4t(vhf[nh][0], vhf[nh][1], vhf[nh][2], vhf[nh][3], vh + o);
                ldmat4t(vlf[nh][0], vlf[nh][1], vlf[nh][2], vlf[nh][3], vl + o);
            }
#pragma unroll
            for (int nf = 0; nf < 8; nf++) {
                int nh = nf >> 1, ng = nf & 1;
                mma16816(Oacc[nf], aPh, vhf[nh][2 * ng], vhf[nh][2 * ng + 1]);
                mma16816(Oacc[nf], aPl, vhf[nh][2 * ng], vhf[nh][2 * ng + 1]);
                mma16816(Oacc[nf], aPh, vlf[nh][2 * ng], vlf[nh][2 * ng + 1]);
            }
        }
    }

    // ---- epilogue: normalize + write ao pairs ----
    float inv0 = 1.0f / l0, inv1 = 1.0f / l1;
    size_t t0 = (tokq + w * 16 + g) * 1024 + zh * 64;
    size_t t1 = t0 + 8 * 1024;
#pragma unroll
    for (int nf = 0; nf < 8; nf++) {
        int c = nf * 8 + tg * 2;
        float o00 = Oacc[nf][0] * inv0, o01 = Oacc[nf][1] * inv0;
        float o10 = Oacc[nf][2] * inv1, o11 = Oacc[nf][3] * inv1;
        __nv_bfloat162 h0 = __float22bfloat162_rn(make_float2(o00, o01));
        __nv_bfloat162 h1 = __float22bfloat162_rn(make_float2(o10, o11));
        __nv_bfloat162 l0v, l1v;
        l0v.x = __float2bfloat16(o00 - __bfloat162float(h0.x));
        l0v.y = __float2bfloat16(o01 - __bfloat162float(h0.y));
        l1v.x = __float2bfloat16(o10 - __bfloat162float(h1.x));
        l1v.y = __float2bfloat16(o11 - __bfloat162float(h1.y));
        *reinterpret_cast<__nv_bfloat162*>(aoh + t0 + c) = h0;
        *reinterpret_cast<__nv_bfloat162*>(aol + t0 + c) = l0v;
        *reinterpret_cast<__nv_bfloat162*>(aoh + t1 + c) = h1;
        *reinterpret_cast<__nv_bfloat162*>(aol + t1 + c) = l1v;
    }
}

// ---------------- launcher ----------------
extern "C" void kernel_launch(void* const* d_in, const int* in_sizes, int n_in,
                              void* d_out, int out_size)
{
    const float* x      = (const float*)d_in[0];
    const float* t_emb  = (const float*)d_in[1];
    const float* rel    = (const float*)d_in[2];
    const int*   amask  = (const int*)d_in[3];
    const float* w_ada  = (const float*)d_in[4];
    const float* b_ada  = (const float*)d_in[5];
    const float* g1     = (const float*)d_in[6];
    const float* be1    = (const float*)d_in[7];
    const float* g2     = (const float*)d_in[8];
    const float* be2    = (const float*)d_in[9];
    const float* w_qkv  = (const float*)d_in[10];
    const float* b_qkv  = (const float*)d_in[11];
    const float* w_proj = (const float*)d_in[12];
    const float* b_proj = (const float*)d_in[13];
    const float* w_rp1  = (const float*)d_in[14];
    const float* b_rp1  = (const float*)d_in[15];
    const float* w_rp2  = (const float*)d_in[16];
    const float* b_rp2  = (const float*)d_in[17];
    const float* w_fc1  = (const float*)d_in[18];
    const float* b_fc1  = (const float*)d_in[19];
    const float* w_fc2  = (const float*)d_in[20];
    const float* b_fc2  = (const float*)d_in[21];
    float* out = (float*)d_out;

    float *mod, *att, *x1;
    __nv_bfloat16 *xnh, *xnl, *qph, *qpl, *aoh, *aol, *hh, *hl;
    __nv_bfloat16 *wqkvh, *wqkvl, *wprojh, *wprojl, *wfc1h, *wfc1l, *wfc2h, *wfc2l;
    cudaGetSymbolAddress((void**)&mod, g_mod);
    cudaGetSymbolAddress((void**)&att, g_att);
    cudaGetSymbolAddress((void**)&x1,  g_x1);
    cudaGetSymbolAddress((void**)&xnh, g_xnh);
    cudaGetSymbolAddress((void**)&xnl, g_xnl);
    cudaGetSymbolAddress((void**)&qph, g_qkvph);
    cudaGetSymbolAddress((void**)&qpl, g_qkvpl);
    cudaGetSymbolAddress((void**)&aoh, g_aoh);
    cudaGetSymbolAddress((void**)&aol, g_aol);
    cudaGetSymbolAddress((void**)&hh,  g_hh);
    cudaGetSymbolAddress((void**)&hl,  g_hl);
    cudaGetSymbolAddress((void**)&wqkvh, g_wqkvh);
    cudaGetSymbolAddress((void**)&wqkvl, g_wqkvl);
    cudaGetSymbolAddress((void**)&wprojh, g_wprojh);
    cudaGetSymbolAddress((void**)&wprojl, g_wprojl);
    cudaGetSymbolAddress((void**)&wfc1h, g_wfc1h);
    cudaGetSymbolAddress((void**)&wfc1l, g_wfc1l);
    cudaGetSymbolAddress((void**)&wfc2h, g_wfc2h);
    cudaGetSymbolAddress((void**)&wfc2l, g_wfc2l);

    cudaFuncSetAttribute(hmma_gemm<TEPI_BIASP>,   cudaFuncAttributeMaxDynamicSharedMemorySize, HG_SMEM);
    cudaFuncSetAttribute(hmma_gemm<TEPI_GELUP>,   cudaFuncAttributeMaxDynamicSharedMemorySize, HG_SMEM);
    cudaFuncSetAttribute(hmma_gemm<TEPI_RESGATE>, cudaFuncAttributeMaxDynamicSharedMemorySize, HG_SMEM);
    cudaFuncSetAttribute(fused_attn,              cudaFuncAttributeMaxDynamicSharedMemorySize, FA_SMEM);

    // weight splits
    split_kernel<<<3072, 256>>>(w_qkv,  wqkvh,  wqkvl,  3072 * 1024 / 4);
    split_kernel<<<1024, 256>>>(w_proj, wprojh, wprojl, 1024 * 1024 / 4);
    split_kernel<<<4096, 256>>>(w_fc1,  wfc1h,  wfc1l,  4096 * 1024 / 4);
    split_kernel<<<4096, 256>>>(w_fc2,  wfc2h,  wfc2l,  4096 * 1024 / 4);

    // 1. adaLN modulation
    ada_kernel<<<768, 256>>>(t_emb, w_ada, b_ada, mod);
    // 2. LN1 + modulate
    ln_mod_kernel<<<2048, 256>>>(x, g1, be1, mod, 0, 1, xnh, xnl);
    // 3. qkv -> bf16 pairs
    hmma_gemm<TEPI_BIASP><<<dim3(24, 16), 256, HG_SMEM>>>(
        xnh, xnl, 1024, wqkvh, wqkvl, 1024, nullptr, 0, 1024,
        b_qkv, nullptr, nullptr, qph, qpl, 3072);
    // 4. rel-pos bias
    relpos_kernel<<<4096, 256>>>(rel, w_rp1, b_rp1, w_rp2, b_rp2, att);
    // 5. fused attention -> ao pairs
    fused_attn<<<dim3(64, 4), 256, FA_SMEM>>>(qph, qpl, att, amask, aoh, aol);
    // 6. proj + gated residual
    hmma_gemm<TEPI_RESGATE><<<dim3(8, 16), 256, HG_SMEM>>>(
        aoh, aol, 1024, wprojh, wprojl, 1024, x1, 1024, 1024,
        b_proj, x, mod + 2048, nullptr, nullptr, 0);
    // 7. LN2 + modulate
    ln_mod_kernel<<<2048, 256>>>(x1, g2, be2, mod, 3, 4, xnh, xnl);
    // 8. fc1 + gelu -> pairs
    hmma_gemm<TEPI_GELUP><<<dim3(32, 16), 256, HG_SMEM>>>(
        xnh, xnl, 1024, wfc1h, wfc1l, 1024, nullptr, 0, 1024,
        b_fc1, nullptr, nullptr, hh, hl, 4096);
    // 9. fc2 + gated residual -> out
    hmma_gemm<TEPI_RESGATE><<<dim3(8, 16), 256, HG_SMEM>>>(
        hh, hl, 4096, wfc2h, wfc2l, 4096, out, 1024, 4096,
        b_fc2, x1, mod + 5120, nullptr, nullptr, 0);
}

// round 14
// speedup vs baseline: 1.0912x; 1.0094x over previous
#include <cuda_runtime.h>
#include <cuda_bf16.h>
#include <math.h>
#include <stdint.h>

// B=4, N=512, D=1024, H=16, HD=64, HID=4096, RP_HID=64; tokens M=2048

#define TEPI_BIASP   0
#define TEPI_GELUP   1
#define TEPI_RESGATE 2

// ---------------- scratch ----------------
__device__ float g_mod[4 * 6144];
__device__ float g_att[4 * 16 * 512 * 512];
__device__ float g_x1[2048 * 1024];
__device__ __nv_bfloat16 g_xnh[2048 * 1024], g_xnl[2048 * 1024];
__device__ __nv_bfloat16 g_qkvph[2048 * 3072], g_qkvpl[2048 * 3072];
__device__ __nv_bfloat16 g_aoh[2048 * 1024], g_aol[2048 * 1024];
__device__ __nv_bfloat16 g_hh[2048 * 4096], g_hl[2048 * 4096];
__device__ __nv_bfloat16 g_wqkvh[3072 * 1024], g_wqkvl[3072 * 1024];
__device__ __nv_bfloat16 g_wprojh[1024 * 1024], g_wprojl[1024 * 1024];
__device__ __nv_bfloat16 g_wfc1h[4096 * 1024], g_wfc1l[4096 * 1024];
__device__ __nv_bfloat16 g_wfc2h[1024 * 4096], g_wfc2l[1024 * 4096];

// ---------------- helpers ----------------
__device__ __forceinline__ uint32_t smem_u32(const void* p) {
    uint32_t a;
    asm("{ .reg .u64 t; cvta.to.shared.u64 t, %1; cvt.u32.u64 %0, t; }" : "=r"(a) : "l"(p));
    return a;
}
__device__ __forceinline__ void cp16(uint32_t s, const void* g) {
    asm volatile("cp.async.cg.shared.global [%0], [%1], 16;" :: "r"(s), "l"(g));
}
__device__ __forceinline__ void cp_commit() {
    asm volatile("cp.async.commit_group;" ::: "memory");
}
__device__ __forceinline__ void cp_wait0() {
    asm volatile("cp.async.wait_group 0;" ::: "memory");
}
__device__ __forceinline__ void cp_wait1() {
    asm volatile("cp.async.wait_group 1;" ::: "memory");
}
__device__ __forceinline__ void ldmat4(uint32_t& r0, uint32_t& r1, uint32_t& r2, uint32_t& r3, uint32_t a) {
    asm volatile("ldmatrix.sync.aligned.m8n8.x4.shared.b16 {%0,%1,%2,%3}, [%4];"
                 : "=r"(r0), "=r"(r1), "=r"(r2), "=r"(r3) : "r"(a));
}
__device__ __forceinline__ void ldmat4t(uint32_t& r0, uint32_t& r1, uint32_t& r2, uint32_t& r3, uint32_t a) {
    asm volatile("ldmatrix.sync.aligned.m8n8.x4.trans.shared.b16 {%0,%1,%2,%3}, [%4];"
                 : "=r"(r0), "=r"(r1), "=r"(r2), "=r"(r3) : "r"(a));
}
__device__ __forceinline__ void mma16816(float* c, const uint32_t* a, uint32_t b0, uint32_t b1) {
    asm volatile(
        "mma.sync.aligned.m16n8k16.row.col.f32.bf16.bf16.f32 "
        "{%0,%1,%2,%3}, {%4,%5,%6,%7}, {%8,%9}, {%0,%1,%2,%3};"
        : "+f"(c[0]), "+f"(c[1]), "+f"(c[2]), "+f"(c[3])
        : "r"(a[0]), "r"(a[1]), "r"(a[2]), "r"(a[3]), "r"(b0), "r"(b1));
}
__device__ __forceinline__ uint32_t packbf2(float a, float b) {
    __nv_bfloat162 h = __float22bfloat162_rn(make_float2(a, b));
    return *reinterpret_cast<uint32_t*>(&h);
}

// ---------------- adaLN ----------------
__global__ __launch_bounds__(256) void ada_kernel(
    const float* __restrict__ t_emb, const float* __restrict__ w_ada,
    const float* __restrict__ b_ada, float* __restrict__ mod)
{
    __shared__ float sh[4096];
    int tid = threadIdx.x;
    for (int i = tid; i < 4096; i += 256) {
        float t = t_emb[i];
        sh[i] = t / (1.0f + __expf(-t));
    }
    __syncthreads();
    int j = blockIdx.x * 8 + (tid >> 5);
    int lane = tid & 31;
    const float* wr = w_ada + (size_t)j * 1024;
    float a0 = 0.f, a1 = 0.f, a2 = 0.f, a3 = 0.f;
    for (int k = lane; k < 1024; k += 32) {
        float w = wr[k];
        a0 = fmaf(w, sh[k], a0);
        a1 = fmaf(w, sh[1024 + k], a1);
        a2 = fmaf(w, sh[2048 + k], a2);
        a3 = fmaf(w, sh[3072 + k], a3);
    }
    for (int o = 16; o; o >>= 1) {
        a0 += __shfl_xor_sync(0xffffffffu, a0, o);
        a1 += __shfl_xor_sync(0xffffffffu, a1, o);
        a2 += __shfl_xor_sync(0xffffffffu, a2, o);
        a3 += __shfl_xor_sync(0xffffffffu, a3, o);
    }
    if (lane == 0) {
        float bb = b_ada[j];
        mod[j]            = a0 + bb;
        mod[6144 + j]     = a1 + bb;
        mod[2 * 6144 + j] = a2 + bb;
        mod[3 * 6144 + j] = a3 + bb;
    }
}

// ---------------- LN + modulation -> bf16 pair ----------------
__global__ __launch_bounds__(256) void ln_mod_kernel(
    const float* __restrict__ xin, const float* __restrict__ gamma,
    const float* __restrict__ beta, const float* __restrict__ mod,
    int shift_chunk, int scale_chunk,
    __nv_bfloat16* __restrict__ outh, __nv_bfloat16* __restrict__ outl)
{
    int token = blockIdx.x;
    int b = token >> 9;
    int tid = threadIdx.x;
    const float* xr = xin + (size_t)token * 1024;
    float v[4];
    float s = 0.f, sq = 0.f;
#pragma unroll
    for (int i = 0; i < 4; i++) {
        float t = xr[i * 256 + tid];
        v[i] = t; s += t; sq += t * t;
    }
    for (int o = 16; o; o >>= 1) {
        s  += __shfl_xor_sync(0xffffffffu, s, o);
        sq += __shfl_xor_sync(0xffffffffu, sq, o);
    }
    __shared__ float ss[8], ssq[8], smu, srstd;
    int wid = tid >> 5, lane = tid & 31;
    if (lane == 0) { ss[wid] = s; ssq[wid] = sq; }
    __syncthreads();
    if (tid == 0) {
        float S = 0.f, Q = 0.f;
        for (int i = 0; i < 8; i++) { S += ss[i]; Q += ssq[i]; }
        float mu = S * (1.0f / 1024.0f);
        float var = Q * (1.0f / 1024.0f) - mu * mu;
        smu = mu; srstd = rsqrtf(var + 1e-5f);
    }
    __syncthreads();
    float mu = smu, rstd = srstd;
    const float* modb = mod + (size_t)b * 6144;
    const float* shm = modb + shift_chunk * 1024;
    const float* scm = modb + scale_chunk * 1024;
    size_t rb = (size_t)token * 1024;
#pragma unroll
    for (int i = 0; i < 4; i++) {
        int c = i * 256 + tid;
        float ln = (v[i] - mu) * rstd * gamma[c] + beta[c];
        float o = ln * (1.0f + scm[c]) + shm[c];
        __nv_bfloat16 h = __float2bfloat16(o);
        outh[rb + c] = h;
        outl[rb + c] = __float2bfloat16(o - __bfloat162float(h));
    }
}

// ---------------- split fp32 -> bf16 pair (weights) ----------------
__global__ __launch_bounds__(256) void split_kernel(
    const float* __restrict__ src, __nv_bfloat16* __restrict__ hi,
    __nv_bfloat16* __restrict__ lo, int n4)
{
    int i = blockIdx.x * 256 + threadIdx.x;
    if (i >= n4) return;
    float4 v = reinterpret_cast<const float4*>(src)[i];
    __nv_bfloat16 h0 = __float2bfloat16(v.x), h1 = __float2bfloat16(v.y);
    __nv_bfloat16 h2 = __float2bfloat16(v.z), h3 = __float2bfloat16(v.w);
    __nv_bfloat162 H0; H0.x = h0; H0.y = h1;
    __nv_bfloat162 H1; H1.x = h2; H1.y = h3;
    __nv_bfloat162 L0, L1;
    L0.x = __float2bfloat16(v.x - __bfloat162float(h0));
    L0.y = __float2bfloat16(v.y - __bfloat162float(h1));
    L1.x = __float2bfloat16(v.z - __bfloat162float(h2));
    L1.y = __float2bfloat16(v.w - __bfloat162float(h3));
    reinterpret_cast<__nv_bfloat162*>(hi)[2 * i]     = H0;
    reinterpret_cast<__nv_bfloat162*>(hi)[2 * i + 1] = H1;
    reinterpret_cast<__nv_bfloat162*>(lo)[2 * i]     = L0;
    reinterpret_cast<__nv_bfloat162*>(lo)[2 * i + 1] = L1;
}

// ---------------- rel-pos bias MLP ----------------
__global__ __launch_bounds__(256) void relpos_kernel(
    const float* __restrict__ rel, const float* __restrict__ w1,
    const float* __restrict__ b1, const float* __restrict__ w2,
    const float* __restrict__ b2, float* __restrict__ out)
{
    __shared__ float sw1[128], sb1[64], sw2[1024], sb2[16];
    int tid = threadIdx.x;
    if (tid < 128) sw1[tid] = w1[tid];
    if (tid < 64)  sb1[tid] = b1[tid];
    for (int i = tid; i < 1024; i += 256) sw2[i] = w2[i];
    if (tid < 16)  sb2[tid] = b2[tid];
    __syncthreads();
    int gid = blockIdx.x * 256 + tid;
    float r0 = rel[2 * (size_t)gid];
    float r1 = rel[2 * (size_t)gid + 1];
    float h[64];
#pragma unroll
    for (int u = 0; u < 64; u++)
        h[u] = fmaxf(fmaf(sw1[2 * u], r0, fmaf(sw1[2 * u + 1], r1, sb1[u])), 0.0f);
    int b = gid >> 18;
    int rem = gid & 262143;
    size_t base = ((size_t)b << 22) + (size_t)rem;
#pragma unroll
    for (int hh = 0; hh < 16; hh++) {
        float s2 = sb2[hh];
#pragma unroll
        for (int u = 0; u < 64; u++)
            s2 = fmaf(h[u], sw2[hh * 64 + u], s2);
        out[base + ((size_t)hh << 18)] = s2;
    }
}

// ---------------- HMMA bf16x3 GEMM (NT): C = A[M,K] @ B[N,K]^T ----------------
// MI=2: CTA 128x128, warp 32x64. MI=1: CTA 64x128, warp 16x64.
// 3-stage cp.async pipeline, 1 __syncthreads per chunk. 2 CTAs/SM.
template<int MI> struct HGDims {
    static constexpr int BM   = 64 * MI;
    static constexpr int STG  = (BM + 128) * 80;
    static constexpr int EPIB = BM * 132 * 4;
    static constexpr int SMEM = (3 * STG > EPIB) ? 3 * STG : EPIB;
};

template<int EPI, int MI>
__global__ __launch_bounds__(256, 2) void hmma_gemm(
    const __nv_bfloat16* __restrict__ Ah, const __nv_bfloat16* __restrict__ Al, int lda,
    const __nv_bfloat16* __restrict__ Bh, const __nv_bfloat16* __restrict__ Bl, int ldb,
    float* __restrict__ C, int ldc, int K,
    const float* __restrict__ bias, const float* __restrict__ res,
    const float* __restrict__ gate,
    __nv_bfloat16* __restrict__ outh, __nv_bfloat16* __restrict__ outl, int ldo)
{
    constexpr int BM  = HGDims<MI>::BM;
    constexpr int STG = HGDims<MI>::STG;
    extern __shared__ char smem[];
    uint32_t sbase = smem_u32(smem);
    int tid = threadIdx.x;
    int m0 = blockIdx.y * BM;
    int n0 = blockIdx.x * 128;

    int w = tid >> 5;
    int lane = tid & 31;
    int wm0 = (w & 3) * 16 * MI;
    int wn0 = (w >> 2) * 64;
    int mm = lane >> 3, rr = lane & 7;
    int aRowOff = wm0 + ((mm & 1) << 3) + rr;
    int aByte   = (mm >> 1) << 4;
    int bRowOff = wn0 + ((mm >> 1) << 3) + rr;
    int bByte   = (mm & 1) << 4;

    float acc[MI][8][4];
#pragma unroll
    for (int mi = 0; mi < MI; mi++)
#pragma unroll
        for (int ni = 0; ni < 8; ni++)
#pragma unroll
            for (int q = 0; q < 4; q++) acc[mi][ni][q] = 0.0f;

    int nc = (3 * K) >> 5;

    auto load_chunk = [&](int c, int s) {
        int kk = c << 5;
        int blk = (kk >= K) + (kk >= 2 * K);
        int koff = kk - blk * K;
        const __nv_bfloat16* pA = (blk == 1) ? Al : Ah;
        const __nv_bfloat16* pB = (blk == 2) ? Bl : Bh;
        uint32_t sA = sbase + s * STG;
        uint32_t sB = sA + BM * 80;
#pragma unroll
        for (int u = 0; u < MI; u++) {   // A: BM*4 cp16
            int i = u * 256 + tid;
            int ch = i / BM, r = i % BM;
            cp16(sA + r * 80 + ch * 16, pA + (size_t)(m0 + r) * lda + koff + ch * 8);
        }
#pragma unroll
        for (int u = 0; u < 2; u++) {    // B: 512 cp16
            int i = u * 256 + tid;
            int ch = i >> 7, r = i & 127;
            cp16(sB + r * 80 + ch * 16, pB + (size_t)(n0 + r) * ldb + koff + ch * 8);
        }
        cp_commit();
    };

    load_chunk(0, 0);
    load_chunk(1, 1);
    for (int c = 0; c < nc; c++) {
        int s = c % 3;
        if (c + 1 < nc) cp_wait1(); else cp_wait0();
        __syncthreads();
        if (c + 2 < nc) load_chunk(c + 2, (c + 2) % 3);
        uint32_t sA = sbase + s * STG;
        uint32_t sB = sA + BM * 80;
#pragma unroll
        for (int ks = 0; ks < 2; ks++) {
            uint32_t af[MI][4];
#pragma unroll
            for (int mi = 0; mi < MI; mi++)
                ldmat4(af[mi][0], af[mi][1], af[mi][2], af[mi][3],
                       sA + (uint32_t)(aRowOff + mi * 16) * 80 + ks * 32 + aByte);
            uint32_t bfr[4][4];
#pragma unroll
            for (int bi = 0; bi < 4; bi++)
                ldmat4(bfr[bi][0], bfr[bi][1], bfr[bi][2], bfr[bi][3],
                       sB + (uint32_t)(bRowOff + bi * 16) * 80 + ks * 32 + bByte);
#pragma unroll
            for (int mi = 0; mi < MI; mi++)
#pragma unroll
                for (int ni = 0; ni < 8; ni++) {
                    int bi = ni >> 1, hb = (ni & 1) * 2;
                    mma16816(acc[mi][ni], af[mi], bfr[bi][hb], bfr[bi][hb + 1]);
                }
        }
    }
    __syncthreads();

    float* sC = reinterpret_cast<float*>(smem);
    int g = lane >> 2, tg = lane & 3;
#pragma unroll
    for (int mi = 0; mi < MI; mi++)
#pragma unroll
        for (int ni = 0; ni < 8; ni++) {
            int r0 = wm0 + mi * 16 + g;
            int c0 = wn0 + ni * 8 + tg * 2;
            sC[r0 * 132 + c0]           = acc[mi][ni][0];
            sC[r0 * 132 + c0 + 1]       = acc[mi][ni][1];
            sC[(r0 + 8) * 132 + c0]     = acc[mi][ni][2];
            sC[(r0 + 8) * 132 + c0 + 1] = acc[mi][ni][3];
        }
    __syncthreads();

    for (int i = tid; i < BM * 128; i += 256) {
        int row = i >> 7, col = i & 127;
        int gm = m0 + row, gn = n0 + col;
        float v = sC[row * 132 + col];
        if constexpr (EPI == TEPI_BIASP) {
            v += bias[gn];
            size_t oidx = (size_t)gm * ldo + gn;
            __nv_bfloat16 h = __float2bfloat16(v);
            outh[oidx] = h;
            outl[oidx] = __float2bfloat16(v - __bfloat162float(h));
        } else if constexpr (EPI == TEPI_GELUP) {
            v += bias[gn];
            float gl = 0.5f * v * (1.0f + erff(v * 0.70710678118654752f));
            size_t oidx = (size_t)gm * ldo + gn;
            __nv_bfloat16 h = __float2bfloat16(gl);
            outh[oidx] = h;
            outl[oidx] = __float2bfloat16(gl - __bfloat162float(h));
        } else {  // TEPI_RESGATE
            size_t idx = (size_t)gm * ldc + gn;
            v += bias[gn];
            float gt = gate[(gm >> 9) * 6144 + gn];
            C[idx] = res[idx] + gt * v;
        }
    }
}

// ---------------- fused flash attention ----------------
static constexpr int FA_Q    = 2 * 128 * 144;       // 36864
static constexpr int FA_KV   = 4 * 64 * 144;        // 36864 per stage
static constexpr int FA_SMEM = FA_Q + 3 * FA_KV;    // 147456

__global__ __launch_bounds__(256) void fused_attn(
    const __nv_bfloat16* __restrict__ qph, const __nv_bfloat16* __restrict__ qpl,
    const float* __restrict__ att, const int* __restrict__ amask,
    __nv_bfloat16* __restrict__ aoh, __nv_bfloat16* __restrict__ aol)
{
    extern __shared__ char smem[];
    uint32_t sbase = smem_u32(smem);
    int tid = threadIdx.x;
    int z = blockIdx.x, zb = z >> 4, zh = z & 15;
    int qb = blockIdx.y;
    int w = tid >> 5, lane = tid & 31;
    int g = lane >> 2, tg = lane & 3;
    int mm = lane >> 3, rr = lane & 7;
    size_t tokq = (size_t)(zb * 512 + qb * 128);

    auto load_q = [&]() {
#pragma unroll
        for (int t = 0; t < 8; t++) {
            int idx = t * 256 + tid;
            int arr = idx >> 10;
            int rem = idx & 1023;
            int r = rem >> 3, ch = rem & 7;
            const __nv_bfloat16* src = (arr ? qpl : qph) + (tokq + r) * 3072 + zh * 64 + ch * 8;
            cp16(sbase + arr * 18432 + (uint32_t)r * 144 + ch * 16, src);
        }
    };
    auto load_kv = [&](int j, int s) {
        uint32_t base = sbase + FA_Q + s * FA_KV;
        size_t tokk = (size_t)(zb * 512 + j * 64);
#pragma unroll
        for (int t = 0; t < 8; t++) {
            int idx = t * 256 + tid;
            int arr = idx >> 9;               // 0 Kh,1 Kl,2 Vh,3 Vl
            int rem = idx & 511;
            int r = rem >> 3, ch = rem & 7;
            const __nv_bfloat16* p = (arr & 1) ? qpl : qph;
            int off = (arr < 2) ? 1024 : 2048;
            cp16(base + arr * 9216 + (uint32_t)r * 144 + ch * 16,
                 p + (tokk + r) * 3072 + off + zh * 64 + ch * 8);
        }
        cp_commit();
    };

    load_q();
    load_kv(0, 0);
    load_kv(1, 1);

    uint32_t qfh[4][4], qfl[4][4];
    float Oacc[8][4];
#pragma unroll
    for (int nf = 0; nf < 8; nf++)
#pragma unroll
        for (int q = 0; q < 4; q++) Oacc[nf][q] = 0.0f;
    float m0 = -1e30f, m1 = -1e30f, l0 = 0.0f, l1 = 0.0f;

    int qrow0 = qb * 128 + w * 16 + g;
    const float* bb0 = att + ((size_t)z << 18) + (size_t)qrow0 * 512;
    const float* bb1 = bb0 + 8 * 512;
    const int* mbase = amask + zb * 512;

    bool qloaded = false;
    for (int j = 0; j < 8; j++) {
        int s = j % 3;
        if (j + 1 < 8) cp_wait1(); else cp_wait0();
        __syncthreads();
        if (j + 2 < 8) load_kv(j + 2, (j + 2) % 3);

        if (!qloaded) {
            uint32_t arow = (uint32_t)(w * 16 + ((mm & 1) << 3) + rr) * 144 + ((mm >> 1) << 4);
#pragma unroll
            for (int ks = 0; ks < 4; ks++) {
                ldmat4(qfh[ks][0], qfh[ks][1], qfh[ks][2], qfh[ks][3], sbase + arow + ks * 32);
                ldmat4(qfl[ks][0], qfl[ks][1], qfl[ks][2], qfl[ks][3], sbase + 18432 + arow + ks * 32);
            }
            qloaded = true;
        }

        uint32_t kh = sbase + FA_Q + s * FA_KV;
        uint32_t kl = kh + 9216;
        uint32_t vh = kh + 18432;
        uint32_t vl = kh + 27648;

        float Sacc[8][4];
#pragma unroll
        for (int nf = 0; nf < 8; nf++)
#pragma unroll
            for (int q = 0; q < 4; q++) Sacc[nf][q] = 0.0f;
        uint32_t brow = (uint32_t)(((mm >> 1) << 3) + rr) * 144 + ((mm & 1) << 4);
#pragma unroll
        for (int ks = 0; ks < 4; ks++) {
            uint32_t bh[4][4], bl2[4][4];
#pragma unroll
            for (int kb = 0; kb < 4; kb++) {
                uint32_t o = brow + (uint32_t)kb * (16 * 144) + ks * 32;
                ldmat4(bh[kb][0], bh[kb][1], bh[kb][2], bh[kb][3], kh + o);
                ldmat4(bl2[kb][0], bl2[kb][1], bl2[kb][2], bl2[kb][3], kl + o);
            }
#pragma unroll
            for (int nf = 0; nf < 8; nf++) {
                int kb = nf >> 1, hb = (nf & 1) * 2;
                mma16816(Sacc[nf], qfh[ks], bh[kb][hb], bh[kb][hb + 1]);
                mma16816(Sacc[nf], qfl[ks], bh[kb][hb], bh[kb][hb + 1]);
                mma16816(Sacc[nf], qfh[ks], bl2[kb][hb], bl2[kb][hb + 1]);
            }
        }

        const float* br0 = bb0 + j * 64;
        const float* br1 = bb1 + j * 64;
        const int* mr = mbase + j * 64;
#pragma unroll
        for (int nf = 0; nf < 8; nf++) {
            int c0 = nf * 8 + tg * 2;
            float2 b0 = *reinterpret_cast<const float2*>(br0 + c0);
            float2 b1 = *reinterpret_cast<const float2*>(br1 + c0);
            int2 mv = *reinterpret_cast<const int2*>(mr + c0);
            Sacc[nf][0] = mv.x ? fmaf(Sacc[nf][0], 0.125f, b0.x) : -1e30f;
            Sacc[nf][1] = mv.y ? fmaf(Sacc[nf][1], 0.125f, b0.y) : -1e30f;
            Sacc[nf][2] = mv.x ? fmaf(Sacc[nf][2], 0.125f, b1.x) : -1e30f;
            Sacc[nf][3] = mv.y ? fmaf(Sacc[nf][3], 0.125f, b1.y) : -1e30f;
        }

        float mx0 = -1e30f, mx1 = -1e30f;
#pragma unroll
        for (int nf = 0; nf < 8; nf++) {
            mx0 = fmaxf(mx0, fmaxf(Sacc[nf][0], Sacc[nf][1]));
            mx1 = fmaxf(mx1, fmaxf(Sacc[nf][2], Sacc[nf][3]));
        }
        mx0 = fmaxf(mx0, __shfl_xor_sync(0xffffffffu, mx0, 1));
        mx0 = fmaxf(mx0, __shfl_xor_sync(0xffffffffu, mx0, 2));
        mx1 = fmaxf(mx1, __shfl_xor_sync(0xffffffffu, mx1, 1));
        mx1 = fmaxf(mx1, __shfl_xor_sync(0xffffffffu, mx1, 2));
        float mn0 = fmaxf(m0, mx0), mn1 = fmaxf(m1, mx1);
        float sc0 = __expf(m0 - mn0), sc1 = __expf(m1 - mn1);
        float rs0 = 0.0f, rs1 = 0.0f;
#pragma unroll
        for (int nf = 0; nf < 8; nf++) {
            Sacc[nf][0] = __expf(Sacc[nf][0] - mn0);
            Sacc[nf][1] = __expf(Sacc[nf][1] - mn0);
            Sacc[nf][2] = __expf(Sacc[nf][2] - mn1);
            Sacc[nf][3] = __expf(Sacc[nf][3] - mn1);
            rs0 += Sacc[nf][0] + Sacc[nf][1];
            rs1 += Sacc[nf][2] + Sacc[nf][3];
        }
        rs0 += __shfl_xor_sync(0xffffffffu, rs0, 1);
        rs0 += __shfl_xor_sync(0xffffffffu, rs0, 2);
        rs1 += __shfl_xor_sync(0xffffffffu, rs1, 1);
        rs1 += __shfl_xor_sync(0xffffffffu, rs1, 2);
        l0 = l0 * sc0 + rs0;
        l1 = l1 * sc1 + rs1;
        m0 = mn0; m1 = mn1;
#pragma unroll
        for (int nf = 0; nf < 8; nf++) {
            Oacc[nf][0] *= sc0; Oacc[nf][1] *= sc0;
            Oacc[nf][2] *= sc1; Oacc[nf][3] *= sc1;
        }

        uint32_t vrow = (uint32_t)((((lane >> 3) & 1) << 3) + (lane & 7)) * 144
                      + (uint32_t)((lane >> 4) << 3) * 2;
#pragma unroll
        for (int kk = 0; kk < 4; kk++) {
            uint32_t aPh[4], aPl[4];
            {
                float* f0 = Sacc[2 * kk];
                float* f1 = Sacc[2 * kk + 1];
                aPh[0] = packbf2(f0[0], f0[1]);
                aPh[1] = packbf2(f0[2], f0[3]);
                aPh[2] = packbf2(f1[0], f1[1]);
                aPh[3] = packbf2(f1[2], f1[3]);
                __nv_bfloat162 h0 = *reinterpret_cast<__nv_bfloat162*>(&aPh[0]);
                __nv_bfloat162 h1 = *reinterpret_cast<__nv_bfloat162*>(&aPh[1]);
                __nv_bfloat162 h2 = *reinterpret_cast<__nv_bfloat162*>(&aPh[2]);
                __nv_bfloat162 h3 = *reinterpret_cast<__nv_bfloat162*>(&aPh[3]);
                aPl[0] = packbf2(f0[0] - __bfloat162float(h0.x), f0[1] - __bfloat162float(h0.y));
                aPl[1] = packbf2(f0[2] - __bfloat162float(h1.x), f0[3] - __bfloat162float(h1.y));
                aPl[2] = packbf2(f1[0] - __bfloat162float(h2.x), f1[1] - __bfloat162float(h2.y));
                aPl[3] = packbf2(f1[2] - __bfloat162float(h3.x), f1[3] - __bfloat162float(h3.y));
            }
            uint32_t vhf[4][4], vlf[4][4];
#pragma unroll
            for (int nh = 0; nh < 4; nh++) {
                uint32_t o = (uint32_t)(kk * 16) * 144 + vrow + (uint32_t)(nh * 16) * 2;
                ldmat4t(vhf[nh][0], vhf[nh][1], vhf[nh][2], vhf[nh][3], vh + o);
                ldmat4t(vlf[nh][0], vlf[nh][1], vlf[nh][2], vlf[nh][3], vl + o);
            }
#pragma unroll
            for (int nf = 0; nf < 8; nf++) {
                int nh = nf >> 1, ng = nf & 1;
                mma16816(Oacc[nf], aPh, vhf[nh][2 * ng], vhf[nh][2 * ng + 1]);
                mma16816(Oacc[nf], aPl, vhf[nh][2 * ng], vhf[nh][2 * ng + 1]);
                mma16816(Oacc[nf], aPh, vlf[nh][2 * ng], vlf[nh][2 * ng + 1]);
            }
        }
    }

    float inv0 = 1.0f / l0, inv1 = 1.0f / l1;
    size_t t0 = (tokq + w * 16 + g) * 1024 + zh * 64;
    size_t t1 = t0 + 8 * 1024;
#pragma unroll
    for (int nf = 0; nf < 8; nf++) {
        int c = nf * 8 + tg * 2;
        float o00 = Oacc[nf][0] * inv0, o01 = Oacc[nf][1] * inv0;
        float o10 = Oacc[nf][2] * inv1, o11 = Oacc[nf][3] * inv1;
        __nv_bfloat162 h0 = __float22bfloat162_rn(make_float2(o00, o01));
        __nv_bfloat162 h1 = __float22bfloat162_rn(make_float2(o10, o11));
        __nv_bfloat162 l0v, l1v;
        l0v.x = __float2bfloat16(o00 - __bfloat162float(h0.x));
        l0v.y = __float2bfloat16(o01 - __bfloat162float(h0.y));
        l1v.x = __float2bfloat16(o10 - __bfloat162float(h1.x));
        l1v.y = __float2bfloat16(o11 - __bfloat162float(h1.y));
        *reinterpret_cast<__nv_bfloat162*>(aoh + t0 + c) = h0;
        *reinterpret_cast<__nv_bfloat162*>(aol + t0 + c) = l0v;
        *reinterpret_cast<__nv_bfloat162*>(aoh + t1 + c) = h1;
        *reinterpret_cast<__nv_bfloat162*>(aol + t1 + c) = l1v;
    }
}

// ---------------- launcher ----------------
extern "C" void kernel_launch(void* const* d_in, const int* in_sizes, int n_in,
                              void* d_out, int out_size)
{
    const float* x      = (const float*)d_in[0];
    const float* t_emb  = (const float*)d_in[1];
    const float* rel    = (const float*)d_in[2];
    const int*   amask  = (const int*)d_in[3];
    const float* w_ada  = (const float*)d_in[4];
    const float* b_ada  = (const float*)d_in[5];
    const float* g1     = (const float*)d_in[6];
    const float* be1    = (const float*)d_in[7];
    const float* g2     = (const float*)d_in[8];
    const float* be2    = (const float*)d_in[9];
    const float* w_qkv  = (const float*)d_in[10];
    const float* b_qkv  = (const float*)d_in[11];
    const float* w_proj = (const float*)d_in[12];
    const float* b_proj = (const float*)d_in[13];
    const float* w_rp1  = (const float*)d_in[14];
    const float* b_rp1  = (const float*)d_in[15];
    const float* w_rp2  = (const float*)d_in[16];
    const float* b_rp2  = (const float*)d_in[17];
    const float* w_fc1  = (const float*)d_in[18];
    const float* b_fc1  = (const float*)d_in[19];
    const float* w_fc2  = (const float*)d_in[20];
    const float* b_fc2  = (const float*)d_in[21];
    float* out = (float*)d_out;

    float *mod, *att, *x1;
    __nv_bfloat16 *xnh, *xnl, *qph, *qpl, *aoh, *aol, *hh, *hl;
    __nv_bfloat16 *wqkvh, *wqkvl, *wprojh, *wprojl, *wfc1h, *wfc1l, *wfc2h, *wfc2l;
    cudaGetSymbolAddress((void**)&mod, g_mod);
    cudaGetSymbolAddress((void**)&att, g_att);
    cudaGetSymbolAddress((void**)&x1,  g_x1);
    cudaGetSymbolAddress((void**)&xnh, g_xnh);
    cudaGetSymbolAddress((void**)&xnl, g_xnl);
    cudaGetSymbolAddress((void**)&qph, g_qkvph);
    cudaGetSymbolAddress((void**)&qpl, g_qkvpl);
    cudaGetSymbolAddress((void**)&aoh, g_aoh);
    cudaGetSymbolAddress((void**)&aol, g_aol);
    cudaGetSymbolAddress((void**)&hh,  g_hh);
    cudaGetSymbolAddress((void**)&hl,  g_hl);
    cudaGetSymbolAddress((void**)&wqkvh, g_wqkvh);
    cudaGetSymbolAddress((void**)&wqkvl, g_wqkvl);
    cudaGetSymbolAddress((void**)&wprojh, g_wprojh);
    cudaGetSymbolAddress((void**)&wprojl, g_wprojl);
    cudaGetSymbolAddress((void**)&wfc1h, g_wfc1h);
    cudaGetSymbolAddress((void**)&wfc1l, g_wfc1l);
    cudaGetSymbolAddress((void**)&wfc2h, g_wfc2h);
    cudaGetSymbolAddress((void**)&wfc2l, g_wfc2l);

    constexpr int SM2 = HGDims<2>::SMEM;   // 67584
    constexpr int SM1 = HGDims<1>::SMEM;   // 46080
    cudaFuncSetAttribute(hmma_gemm<TEPI_BIASP, 2>,   cudaFuncAttributeMaxDynamicSharedMemorySize, SM2);
    cudaFuncSetAttribute(hmma_gemm<TEPI_GELUP, 2>,   cudaFuncAttributeMaxDynamicSharedMemorySize, SM2);
    cudaFuncSetAttribute(hmma_gemm<TEPI_RESGATE, 1>, cudaFuncAttributeMaxDynamicSharedMemorySize, SM1);
    cudaFuncSetAttribute(fused_attn,                 cudaFuncAttributeMaxDynamicSharedMemorySize, FA_SMEM);

    // weight splits
    split_kernel<<<3072, 256>>>(w_qkv,  wqkvh,  wqkvl,  3072 * 1024 / 4);
    split_kernel<<<1024, 256>>>(w_proj, wprojh, wprojl, 1024 * 1024 / 4);
    split_kernel<<<4096, 256>>>(w_fc1,  wfc1h,  wfc1l,  4096 * 1024 / 4);
    split_kernel<<<4096, 256>>>(w_fc2,  wfc2h,  wfc2l,  4096 * 1024 / 4);

    // 1. adaLN modulation
    ada_kernel<<<768, 256>>>(t_emb, w_ada, b_ada, mod);
    // 2. LN1 + modulate
    ln_mod_kernel<<<2048, 256>>>(x, g1, be1, mod, 0, 1, xnh, xnl);
    // 3. qkv -> bf16 pairs (BM=128, occ 2)
    hmma_gemm<TEPI_BIASP, 2><<<dim3(24, 16), 256, SM2>>>(
        xnh, xnl, 1024, wqkvh, wqkvl, 1024, nullptr, 0, 1024,
        b_qkv, nullptr, nullptr, qph, qpl, 3072);
    // 4. rel-pos bias
    relpos_kernel<<<4096, 256>>>(rel, w_rp1, b_rp1, w_rp2, b_rp2, att);
    // 5. fused attention -> ao pairs
    fused_attn<<<dim3(64, 4), 256, FA_SMEM>>>(qph, qpl, att, amask, aoh, aol);
    // 6. proj + gated residual (BM=64 -> 256 CTAs)
    hmma_gemm<TEPI_RESGATE, 1><<<dim3(8, 32), 256, SM1>>>(
        aoh, aol, 1024, wprojh, wprojl, 1024, x1, 1024, 1024,
        b_proj, x, mod + 2048, nullptr, nullptr, 0);
    // 7. LN2 + modulate
    ln_mod_kernel<<<2048, 256>>>(x1, g2, be2, mod, 3, 4, xnh, xnl);
    // 8. fc1 + gelu -> pairs (BM=128, occ 2)
    hmma_gemm<TEPI_GELUP, 2><<<dim3(32, 16), 256, SM2>>>(
        xnh, xnl, 1024, wfc1h, wfc1l, 1024, nullptr, 0, 1024,
        b_fc1, nullptr, nullptr, hh, hl, 4096);
    // 9. fc2 + gated residual -> out (BM=64 -> 256 CTAs)
    hmma_gemm<TEPI_RESGATE, 1><<<dim3(8, 32), 256, SM1>>>(
        hh, hl, 4096, wfc2h, wfc2l, 4096, out, 1024, 4096,
        b_fc2, x1, mod + 5120, nullptr, nullptr, 0);
}

// round 17
// speedup vs baseline: 1.3229x; 1.2123x over previous
#include <cuda_runtime.h>
#include <cuda_bf16.h>
#include <math.h>
#include <stdint.h>

// B=4, N=512, D=1024, H=16, HD=64, HID=4096, RP_HID=64; tokens M=2048

#define TEPI_BIASP   0
#define TEPI_GELUP   1
#define TEPI_RESGATE 2

// ---------------- scratch ----------------
__device__ float g_mod[4 * 6144];
__device__ float g_att[4 * 16 * 512 * 512];
__device__ float g_x1[2048 * 1024];
__device__ __nv_bfloat16 g_xnh[2048 * 1024], g_xnl[2048 * 1024];
__device__ __nv_bfloat16 g_qkvph[2048 * 3072], g_qkvpl[2048 * 3072];
__device__ __nv_bfloat16 g_aoh[2048 * 1024], g_aol[2048 * 1024];
__device__ __nv_bfloat16 g_hh[2048 * 4096], g_hl[2048 * 4096];
__device__ __nv_bfloat16 g_wqkvh[3072 * 1024], g_wqkvl[3072 * 1024];
__device__ __nv_bfloat16 g_wprojh[1024 * 1024], g_wprojl[1024 * 1024];
__device__ __nv_bfloat16 g_wfc1h[4096 * 1024], g_wfc1l[4096 * 1024];
__device__ __nv_bfloat16 g_wfc2h[1024 * 4096], g_wfc2l[1024 * 4096];

// ---------------- helpers ----------------
__device__ __forceinline__ uint32_t smem_u32(const void* p) {
    uint32_t a;
    asm("{ .reg .u64 t; cvta.to.shared.u64 t, %1; cvt.u32.u64 %0, t; }" : "=r"(a) : "l"(p));
    return a;
}
__device__ __forceinline__ void cp16(uint32_t s, const void* g) {
    asm volatile("cp.async.cg.shared.global [%0], [%1], 16;" :: "r"(s), "l"(g));
}
__device__ __forceinline__ void cp_commit() {
    asm volatile("cp.async.commit_group;" ::: "memory");
}
__device__ __forceinline__ void cp_wait0() {
    asm volatile("cp.async.wait_group 0;" ::: "memory");
}
__device__ __forceinline__ void cp_wait1() {
    asm volatile("cp.async.wait_group 1;" ::: "memory");
}
__device__ __forceinline__ void ldmat4(uint32_t& r0, uint32_t& r1, uint32_t& r2, uint32_t& r3, uint32_t a) {
    asm volatile("ldmatrix.sync.aligned.m8n8.x4.shared.b16 {%0,%1,%2,%3}, [%4];"
                 : "=r"(r0), "=r"(r1), "=r"(r2), "=r"(r3) : "r"(a));
}
__device__ __forceinline__ void ldmat4t(uint32_t& r0, uint32_t& r1, uint32_t& r2, uint32_t& r3, uint32_t a) {
    asm volatile("ldmatrix.sync.aligned.m8n8.x4.trans.shared.b16 {%0,%1,%2,%3}, [%4];"
                 : "=r"(r0), "=r"(r1), "=r"(r2), "=r"(r3) : "r"(a));
}
__device__ __forceinline__ void mma16816(float* c, const uint32_t* a, uint32_t b0, uint32_t b1) {
    asm volatile(
        "mma.sync.aligned.m16n8k16.row.col.f32.bf16.bf16.f32 "
        "{%0,%1,%2,%3}, {%4,%5,%6,%7}, {%8,%9}, {%0,%1,%2,%3};"
        : "+f"(c[0]), "+f"(c[1]), "+f"(c[2]), "+f"(c[3])
        : "r"(a[0]), "r"(a[1]), "r"(a[2]), "r"(a[3]), "r"(b0), "r"(b1));
}
__device__ __forceinline__ uint32_t packbf2(float a, float b) {
    __nv_bfloat162 h = __float22bfloat162_rn(make_float2(a, b));
    return *reinterpret_cast<uint32_t*>(&h);
}

// ---------------- adaLN ----------------
__global__ __launch_bounds__(256) void ada_kernel(
    const float* __restrict__ t_emb, const float* __restrict__ w_ada,
    const float* __restrict__ b_ada, float* __restrict__ mod)
{
    __shared__ float sh[4096];
    int tid = threadIdx.x;
    for (int i = tid; i < 4096; i += 256) {
        float t = t_emb[i];
        sh[i] = t / (1.0f + __expf(-t));
    }
    __syncthreads();
    int j = blockIdx.x * 8 + (tid >> 5);
    int lane = tid & 31;
    const float* wr = w_ada + (size_t)j * 1024;
    float a0 = 0.f, a1 = 0.f, a2 = 0.f, a3 = 0.f;
    for (int k = lane; k < 1024; k += 32) {
        float w = wr[k];
        a0 = fmaf(w, sh[k], a0);
        a1 = fmaf(w, sh[1024 + k], a1);
        a2 = fmaf(w, sh[2048 + k], a2);
        a3 = fmaf(w, sh[3072 + k], a3);
    }
    for (int o = 16; o; o >>= 1) {
        a0 += __shfl_xor_sync(0xffffffffu, a0, o);
        a1 += __shfl_xor_sync(0xffffffffu, a1, o);
        a2 += __shfl_xor_sync(0xffffffffu, a2, o);
        a3 += __shfl_xor_sync(0xffffffffu, a3, o);
    }
    if (lane == 0) {
        float bb = b_ada[j];
        mod[j]            = a0 + bb;
        mod[6144 + j]     = a1 + bb;
        mod[2 * 6144 + j] = a2 + bb;
        mod[3 * 6144 + j] = a3 + bb;
    }
}

// ---------------- LN + modulation -> bf16 pair ----------------
__global__ __launch_bounds__(256) void ln_mod_kernel(
    const float* __restrict__ xin, const float* __restrict__ gamma,
    const float* __restrict__ beta, const float* __restrict__ mod,
    int shift_chunk, int scale_chunk,
    __nv_bfloat16* __restrict__ outh, __nv_bfloat16* __restrict__ outl)
{
    int token = blockIdx.x;
    int b = token >> 9;
    int tid = threadIdx.x;
    const float* xr = xin + (size_t)token * 1024;
    float v[4];
    float s = 0.f, sq = 0.f;
#pragma unroll
    for (int i = 0; i < 4; i++) {
        float t = xr[i * 256 + tid];
        v[i] = t; s += t; sq += t * t;
    }
    for (int o = 16; o; o >>= 1) {
        s  += __shfl_xor_sync(0xffffffffu, s, o);
        sq += __shfl_xor_sync(0xffffffffu, sq, o);
    }
    __shared__ float ss[8], ssq[8], smu, srstd;
    int wid = tid >> 5, lane = tid & 31;
    if (lane == 0) { ss[wid] = s; ssq[wid] = sq; }
    __syncthreads();
    if (tid == 0) {
        float S = 0.f, Q = 0.f;
        for (int i = 0; i < 8; i++) { S += ss[i]; Q += ssq[i]; }
        float mu = S * (1.0f / 1024.0f);
        float var = Q * (1.0f / 1024.0f) - mu * mu;
        smu = mu; srstd = rsqrtf(var + 1e-5f);
    }
    __syncthreads();
    float mu = smu, rstd = srstd;
    const float* modb = mod + (size_t)b * 6144;
    const float* shm = modb + shift_chunk * 1024;
    const float* scm = modb + scale_chunk * 1024;
    size_t rb = (size_t)token * 1024;
#pragma unroll
    for (int i = 0; i < 4; i++) {
        int c = i * 256 + tid;
        float ln = (v[i] - mu) * rstd * gamma[c] + beta[c];
        float o = ln * (1.0f + scm[c]) + shm[c];
        __nv_bfloat16 h = __float2bfloat16(o);
        outh[rb + c] = h;
        outl[rb + c] = __float2bfloat16(o - __bfloat162float(h));
    }
}

// ---------------- split fp32 -> bf16 pair (weights) ----------------
__global__ __launch_bounds__(256) void split_kernel(
    const float* __restrict__ src, __nv_bfloat16* __restrict__ hi,
    __nv_bfloat16* __restrict__ lo, int n4)
{
    int i = blockIdx.x * 256 + threadIdx.x;
    if (i >= n4) return;
    float4 v = reinterpret_cast<const float4*>(src)[i];
    __nv_bfloat16 h0 = __float2bfloat16(v.x), h1 = __float2bfloat16(v.y);
    __nv_bfloat16 h2 = __float2bfloat16(v.z), h3 = __float2bfloat16(v.w);
    __nv_bfloat162 H0; H0.x = h0; H0.y = h1;
    __nv_bfloat162 H1; H1.x = h2; H1.y = h3;
    __nv_bfloat162 L0, L1;
    L0.x = __float2bfloat16(v.x - __bfloat162float(h0));
    L0.y = __float2bfloat16(v.y - __bfloat162float(h1));
    L1.x = __float2bfloat16(v.z - __bfloat162float(h2));
    L1.y = __float2bfloat16(v.w - __bfloat162float(h3));
    reinterpret_cast<__nv_bfloat162*>(hi)[2 * i]     = H0;
    reinterpret_cast<__nv_bfloat162*>(hi)[2 * i + 1] = H1;
    reinterpret_cast<__nv_bfloat162*>(lo)[2 * i]     = L0;
    reinterpret_cast<__nv_bfloat162*>(lo)[2 * i + 1] = L1;
}

// ---------------- rel-pos bias MLP ----------------
__global__ __launch_bounds__(256) void relpos_kernel(
    const float* __restrict__ rel, const float* __restrict__ w1,
    const float* __restrict__ b1, const float* __restrict__ w2,
    const float* __restrict__ b2, float* __restrict__ out)
{
    __shared__ float sw1[128], sb1[64], sw2[1024], sb2[16];
    int tid = threadIdx.x;
    if (tid < 128) sw1[tid] = w1[tid];
    if (tid < 64)  sb1[tid] = b1[tid];
    for (int i = tid; i < 1024; i += 256) sw2[i] = w2[i];
    if (tid < 16)  sb2[tid] = b2[tid];
    __syncthreads();
    int gid = blockIdx.x * 256 + tid;
    float r0 = rel[2 * (size_t)gid];
    float r1 = rel[2 * (size_t)gid + 1];
    float h[64];
#pragma unroll
    for (int u = 0; u < 64; u++)
        h[u] = fmaxf(fmaf(sw1[2 * u], r0, fmaf(sw1[2 * u + 1], r1, sb1[u])), 0.0f);
    int b = gid >> 18;
    int rem = gid & 262143;
    size_t base = ((size_t)b << 22) + (size_t)rem;
#pragma unroll
    for (int hh = 0; hh < 16; hh++) {
        float s2 = sb2[hh];
#pragma unroll
        for (int u = 0; u < 64; u++)
            s2 = fmaf(h[u], sw2[hh * 64 + u], s2);
        out[base + ((size_t)hh << 18)] = s2;
    }
}

// ---------------- HMMA bf16x3 GEMM (NT): C = A[M,K] @ B[N,K]^T ----------------
// quad-buffer chunks: each 32-K chunk loads {Ah,Al,Bh,Bl} once, issues 3 products.
// 2-stage double buffer, 1 sync/chunk. occ 2.
template<int MI> struct HGDims {
    static constexpr int BM   = 64 * MI;
    static constexpr int STG  = (2 * BM + 256) * 80;   // Ah,Al (BM ea) + Bh,Bl (128 ea)
    static constexpr int EPIB = BM * 132 * 4;
    static constexpr int SMEM = (2 * STG > EPIB) ? 2 * STG : EPIB;
};

template<int EPI, int MI>
__global__ __launch_bounds__(256, 2) void hmma_gemm(
    const __nv_bfloat16* __restrict__ Ah, const __nv_bfloat16* __restrict__ Al, int lda,
    const __nv_bfloat16* __restrict__ Bh, const __nv_bfloat16* __restrict__ Bl, int ldb,
    float* __restrict__ C, int ldc, int K,
    const float* __restrict__ bias, const float* __restrict__ res,
    const float* __restrict__ gate,
    __nv_bfloat16* __restrict__ outh, __nv_bfloat16* __restrict__ outl, int ldo)
{
    constexpr int BM  = HGDims<MI>::BM;
    constexpr int STG = HGDims<MI>::STG;
    extern __shared__ char smem[];
    uint32_t sbase = smem_u32(smem);
    int tid = threadIdx.x;
    int m0 = blockIdx.y * BM;
    int n0 = blockIdx.x * 128;

    int w = tid >> 5;
    int lane = tid & 31;
    int wm0 = (w & 3) * 16 * MI;
    int wn0 = (w >> 2) * 64;
    int mm = lane >> 3, rr = lane & 7;
    int aRowOff = wm0 + ((mm & 1) << 3) + rr;
    int aByte   = (mm >> 1) << 4;
    int bRowOff = wn0 + ((mm >> 1) << 3) + rr;
    int bByte   = (mm & 1) << 4;

    float acc[MI][8][4];
#pragma unroll
    for (int mi = 0; mi < MI; mi++)
#pragma unroll
        for (int ni = 0; ni < 8; ni++)
#pragma unroll
            for (int q = 0; q < 4; q++) acc[mi][ni][q] = 0.0f;

    int nc = K >> 5;

    auto load_chunk = [&](int c, int s) {
        int koff = c << 5;
        uint32_t st = sbase + s * STG;
        // A: Ah,Al  (2*BM*4 cp16)
#pragma unroll
        for (int u = 0; u < 2 * MI; u++) {
            int i = u * 256 + tid;
            int arr = i / (BM * 4);
            int rem = i - arr * (BM * 4);
            int ch = rem / BM, r = rem - ch * BM;
            const __nv_bfloat16* p = arr ? Al : Ah;
            cp16(st + arr * (BM * 80) + r * 80 + ch * 16,
                 p + (size_t)(m0 + r) * lda + koff + ch * 8);
        }
        // B: Bh,Bl  (2*512 cp16)
        uint32_t sB = st + 2 * BM * 80;
#pragma unroll
        for (int u = 0; u < 4; u++) {
            int i = u * 256 + tid;
            int arr = i >> 9, rem = i & 511;
            int ch = rem >> 7, r = rem & 127;
            const __nv_bfloat16* p = arr ? Bl : Bh;
            cp16(sB + arr * (128 * 80) + r * 80 + ch * 16,
                 p + (size_t)(n0 + r) * ldb + koff + ch * 8);
        }
        cp_commit();
    };

    load_chunk(0, 0);
    for (int c = 0; c < nc; c++) {
        int s = c & 1;
        cp_wait0();
        __syncthreads();
        if (c + 1 < nc) load_chunk(c + 1, s ^ 1);
        uint32_t sAh = sbase + s * STG;
        uint32_t sAl = sAh + BM * 80;
        uint32_t sBh = sAh + 2 * BM * 80;
        uint32_t sBl = sBh + 128 * 80;
#pragma unroll
        for (int ks = 0; ks < 2; ks++) {
            uint32_t afh[MI][4], afl[MI][4];
#pragma unroll
            for (int mi = 0; mi < MI; mi++) {
                uint32_t ao = (uint32_t)(aRowOff + mi * 16) * 80 + ks * 32 + aByte;
                ldmat4(afh[mi][0], afh[mi][1], afh[mi][2], afh[mi][3], sAh + ao);
                ldmat4(afl[mi][0], afl[mi][1], afl[mi][2], afl[mi][3], sAl + ao);
            }
#pragma unroll
            for (int bi = 0; bi < 4; bi++) {
                uint32_t bo = (uint32_t)(bRowOff + bi * 16) * 80 + ks * 32 + bByte;
                uint32_t bh[4], bl[4];
                ldmat4(bh[0], bh[1], bh[2], bh[3], sBh + bo);
                ldmat4(bl[0], bl[1], bl[2], bl[3], sBl + bo);
#pragma unroll
                for (int mi = 0; mi < MI; mi++) {
                    mma16816(acc[mi][2 * bi],     afh[mi], bh[0], bh[1]);
                    mma16816(acc[mi][2 * bi + 1], afh[mi], bh[2], bh[3]);
                    mma16816(acc[mi][2 * bi],     afl[mi], bh[0], bh[1]);
                    mma16816(acc[mi][2 * bi + 1], afl[mi], bh[2], bh[3]);
                    mma16816(acc[mi][2 * bi],     afh[mi], bl[0], bl[1]);
                    mma16816(acc[mi][2 * bi + 1], afh[mi], bl[2], bl[3]);
                }
            }
        }
    }
    __syncthreads();

    float* sC = reinterpret_cast<float*>(smem);
    int g = lane >> 2, tg = lane & 3;
#pragma unroll
    for (int mi = 0; mi < MI; mi++)
#pragma unroll
        for (int ni = 0; ni < 8; ni++) {
            int r0 = wm0 + mi * 16 + g;
            int c0 = wn0 + ni * 8 + tg * 2;
            sC[r0 * 132 + c0]           = acc[mi][ni][0];
            sC[r0 * 132 + c0 + 1]       = acc[mi][ni][1];
            sC[(r0 + 8) * 132 + c0]     = acc[mi][ni][2];
            sC[(r0 + 8) * 132 + c0 + 1] = acc[mi][ni][3];
        }
    __syncthreads();

    for (int i = tid; i < BM * 128; i += 256) {
        int row = i >> 7, col = i & 127;
        int gm = m0 + row, gn = n0 + col;
        float v = sC[row * 132 + col];
        if constexpr (EPI == TEPI_BIASP) {
            v += bias[gn];
            size_t oidx = (size_t)gm * ldo + gn;
            __nv_bfloat16 h = __float2bfloat16(v);
            outh[oidx] = h;
            outl[oidx] = __float2bfloat16(v - __bfloat162float(h));
        } else if constexpr (EPI == TEPI_GELUP) {
            v += bias[gn];
            float gl = 0.5f * v * (1.0f + erff(v * 0.70710678118654752f));
            size_t oidx = (size_t)gm * ldo + gn;
            __nv_bfloat16 h = __float2bfloat16(gl);
            outh[oidx] = h;
            outl[oidx] = __float2bfloat16(gl - __bfloat162float(h));
        } else {  // TEPI_RESGATE
            size_t idx = (size_t)gm * ldc + gn;
            v += bias[gn];
            float gt = gate[(gm >> 9) * 6144 + gn];
            C[idx] = res[idx] + gt * v;
        }
    }
}

// ---------------- fused flash attention ----------------
static constexpr int FA_Q    = 2 * 128 * 144;       // 36864
static constexpr int FA_KV   = 4 * 64 * 144;        // 36864 per stage
static constexpr int FA_SMEM = FA_Q + 3 * FA_KV;    // 147456

__global__ __launch_bounds__(256) void fused_attn(
    const __nv_bfloat16* __restrict__ qph, const __nv_bfloat16* __restrict__ qpl,
    const float* __restrict__ att, const int* __restrict__ amask,
    __nv_bfloat16* __restrict__ aoh, __nv_bfloat16* __restrict__ aol)
{
    extern __shared__ char smem[];
    uint32_t sbase = smem_u32(smem);
    int tid = threadIdx.x;
    int z = blockIdx.x, zb = z >> 4, zh = z & 15;
    int qb = blockIdx.y;
    int w = tid >> 5, lane = tid & 31;
    int g = lane >> 2, tg = lane & 3;
    int mm = lane >> 3, rr = lane & 7;
    size_t tokq = (size_t)(zb * 512 + qb * 128);

    auto load_q = [&]() {
#pragma unroll
        for (int t = 0; t < 8; t++) {
            int idx = t * 256 + tid;
            int arr = idx >> 10;
            int rem = idx & 1023;
            int r = rem >> 3, ch = rem & 7;
            const __nv_bfloat16* src = (arr ? qpl : qph) + (tokq + r) * 3072 + zh * 64 + ch * 8;
            cp16(sbase + arr * 18432 + (uint32_t)r * 144 + ch * 16, src);
        }
    };
    auto load_kv = [&](int j, int s) {
        uint32_t base = sbase + FA_Q + s * FA_KV;
        size_t tokk = (size_t)(zb * 512 + j * 64);
#pragma unroll
        for (int t = 0; t < 8; t++) {
            int idx = t * 256 + tid;
            int arr = idx >> 9;               // 0 Kh,1 Kl,2 Vh,3 Vl
            int rem = idx & 511;
            int r = rem >> 3, ch = rem & 7;
            const __nv_bfloat16* p = (arr & 1) ? qpl : qph;
            int off = (arr < 2) ? 1024 : 2048;
            cp16(base + arr * 9216 + (uint32_t)r * 144 + ch * 16,
                 p + (tokk + r) * 3072 + off + zh * 64 + ch * 8);
        }
        cp_commit();
    };

    load_q();
    load_kv(0, 0);
    load_kv(1, 1);

    uint32_t qfh[4][4], qfl[4][4];
    float Oacc[8][4];
#pragma unroll
    for (int nf = 0; nf < 8; nf++)
#pragma unroll
        for (int q = 0; q < 4; q++) Oacc[nf][q] = 0.0f;
    float m0 = -1e30f, m1 = -1e30f, l0 = 0.0f, l1 = 0.0f;

    int qrow0 = qb * 128 + w * 16 + g;
    const float* bb0 = att + ((size_t)z << 18) + (size_t)qrow0 * 512;
    const float* bb1 = bb0 + 8 * 512;
    const int* mbase = amask + zb * 512;

    bool qloaded = false;
    for (int j = 0; j < 8; j++) {
        int s = j % 3;
        if (j + 1 < 8) cp_wait1(); else cp_wait0();
        __syncthreads();
        if (j + 2 < 8) load_kv(j + 2, (j + 2) % 3);

        if (!qloaded) {
            uint32_t arow = (uint32_t)(w * 16 + ((mm & 1) << 3) + rr) * 144 + ((mm >> 1) << 4);
#pragma unroll
            for (int ks = 0; ks < 4; ks++) {
                ldmat4(qfh[ks][0], qfh[ks][1], qfh[ks][2], qfh[ks][3], sbase + arow + ks * 32);
                ldmat4(qfl[ks][0], qfl[ks][1], qfl[ks][2], qfl[ks][3], sbase + 18432 + arow + ks * 32);
            }
            qloaded = true;
        }

        uint32_t kh = sbase + FA_Q + s * FA_KV;
        uint32_t kl = kh + 9216;
        uint32_t vh = kh + 18432;
        uint32_t vl = kh + 27648;

        float Sacc[8][4];
#pragma unroll
        for (int nf = 0; nf < 8; nf++)
#pragma unroll
            for (int q = 0; q < 4; q++) Sacc[nf][q] = 0.0f;
        uint32_t brow = (uint32_t)(((mm >> 1) << 3) + rr) * 144 + ((mm & 1) << 4);
#pragma unroll
        for (int ks = 0; ks < 4; ks++) {
            uint32_t bh[4][4], bl2[4][4];
#pragma unroll
            for (int kb = 0; kb < 4; kb++) {
                uint32_t o = brow + (uint32_t)kb * (16 * 144) + ks * 32;
                ldmat4(bh[kb][0], bh[kb][1], bh[kb][2], bh[kb][3], kh + o);
                ldmat4(bl2[kb][0], bl2[kb][1], bl2[kb][2], bl2[kb][3], kl + o);
            }
#pragma unroll
            for (int nf = 0; nf < 8; nf++) {
                int kb = nf >> 1, hb = (nf & 1) * 2;
                mma16816(Sacc[nf], qfh[ks], bh[kb][hb], bh[kb][hb + 1]);
                mma16816(Sacc[nf], qfl[ks], bh[kb][hb], bh[kb][hb + 1]);
                mma16816(Sacc[nf], qfh[ks], bl2[kb][hb], bl2[kb][hb + 1]);
            }
        }

        const float* br0 = bb0 + j * 64;
        const float* br1 = bb1 + j * 64;
        const int* mr = mbase + j * 64;
#pragma unroll
        for (int nf = 0; nf < 8; nf++) {
            int c0 = nf * 8 + tg * 2;
            float2 b0 = *reinterpret_cast<const float2*>(br0 + c0);
            float2 b1 = *reinterpret_cast<const float2*>(br1 + c0);
            int2 mv = *reinterpret_cast<const int2*>(mr + c0);
            Sacc[nf][0] = mv.x ? fmaf(Sacc[nf][0], 0.125f, b0.x) : -1e30f;
            Sacc[nf][1] = mv.y ? fmaf(Sacc[nf][1], 0.125f, b0.y) : -1e30f;
            Sacc[nf][2] = mv.x ? fmaf(Sacc[nf][2], 0.125f, b1.x) : -1e30f;
            Sacc[nf][3] = mv.y ? fmaf(Sacc[nf][3], 0.125f, b1.y) : -1e30f;
        }

        float mx0 = -1e30f, mx1 = -1e30f;
#pragma unroll
        for (int nf = 0; nf < 8; nf++) {
            mx0 = fmaxf(mx0, fmaxf(Sacc[nf][0], Sacc[nf][1]));
            mx1 = fmaxf(mx1, fmaxf(Sacc[nf][2], Sacc[nf][3]));
        }
        mx0 = fmaxf(mx0, __shfl_xor_sync(0xffffffffu, mx0, 1));
        mx0 = fmaxf(mx0, __shfl_xor_sync(0xffffffffu, mx0, 2));
        mx1 = fmaxf(mx1, __shfl_xor_sync(0xffffffffu, mx1, 1));
        mx1 = fmaxf(mx1, __shfl_xor_sync(0xffffffffu, mx1, 2));
        float mn0 = fmaxf(m0, mx0), mn1 = fmaxf(m1, mx1);
        float sc0 = __expf(m0 - mn0), sc1 = __expf(m1 - mn1);
        float rs0 = 0.0f, rs1 = 0.0f;
#pragma unroll
        for (int nf = 0; nf < 8; nf++) {
            Sacc[nf][0] = __expf(Sacc[nf][0] - mn0);
            Sacc[nf][1] = __expf(Sacc[nf][1] - mn0);
            Sacc[nf][2] = __expf(Sacc[nf][2] - mn1);
            Sacc[nf][3] = __expf(Sacc[nf][3] - mn1);
            rs0 += Sacc[nf][0] + Sacc[nf][1];
            rs1 += Sacc[nf][2] + Sacc[nf][3];
        }
        rs0 += __shfl_xor_sync(0xffffffffu, rs0, 1);
        rs0 += __shfl_xor_sync(0xffffffffu, rs0, 2);
        rs1 += __shfl_xor_sync(0xffffffffu, rs1, 1);
        rs1 += __shfl_xor_sync(0xffffffffu, rs1, 2);
        l0 = l0 * sc0 + rs0;
        l1 = l1 * sc1 + rs1;
        m0 = mn0; m1 = mn1;
#pragma unroll
        for (int nf = 0; nf < 8; nf++) {
            Oacc[nf][0] *= sc0; Oacc[nf][1] *= sc0;
            Oacc[nf][2] *= sc1; Oacc[nf][3] *= sc1;
        }

        uint32_t vrow = (uint32_t)((((lane >> 3) & 1) << 3) + (lane & 7)) * 144
                      + (uint32_t)((lane >> 4) << 3) * 2;
#pragma unroll
        for (int kk = 0; kk < 4; kk++) {
            uint32_t aPh[4], aPl[4];
            {
                float* f0 = Sacc[2 * kk];
                float* f1 = Sacc[2 * kk + 1];
                aPh[0] = packbf2(f0[0], f0[1]);
                aPh[1] = packbf2(f0[2], f0[3]);
                aPh[2] = packbf2(f1[0], f1[1]);
                aPh[3] = packbf2(f1[2], f1[3]);
                __nv_bfloat162 h0 = *reinterpret_cast<__nv_bfloat162*>(&aPh[0]);
                __nv_bfloat162 h1 = *reinterpret_cast<__nv_bfloat162*>(&aPh[1]);
                __nv_bfloat162 h2 = *reinterpret_cast<__nv_bfloat162*>(&aPh[2]);
                __nv_bfloat162 h3 = *reinterpret_cast<__nv_bfloat162*>(&aPh[3]);
                aPl[0] = packbf2(f0[0] - __bfloat162float(h0.x), f0[1] - __bfloat162float(h0.y));
                aPl[1] = packbf2(f0[2] - __bfloat162float(h1.x), f0[3] - __bfloat162float(h1.y));
                aPl[2] = packbf2(f1[0] - __bfloat162float(h2.x), f1[1] - __bfloat162float(h2.y));
                aPl[3] = packbf2(f1[2] - __bfloat162float(h3.x), f1[3] - __bfloat162float(h3.y));
            }
            uint32_t vhf[4][4], vlf[4][4];
#pragma unroll
            for (int nh = 0; nh < 4; nh++) {
                uint32_t o = (uint32_t)(kk * 16) * 144 + vrow + (uint32_t)(nh * 16) * 2;
                ldmat4t(vhf[nh][0], vhf[nh][1], vhf[nh][2], vhf[nh][3], vh + o);
                ldmat4t(vlf[nh][0], vlf[nh][1], vlf[nh][2], vlf[nh][3], vl + o);
            }
#pragma unroll
            for (int nf = 0; nf < 8; nf++) {
                int nh = nf >> 1, ng = nf & 1;
                mma16816(Oacc[nf], aPh, vhf[nh][2 * ng], vhf[nh][2 * ng + 1]);
                mma16816(Oacc[nf], aPl, vhf[nh][2 * ng], vhf[nh][2 * ng + 1]);
                mma16816(Oacc[nf], aPh, vlf[nh][2 * ng], vlf[nh][2 * ng + 1]);
            }
        }
    }

    float inv0 = 1.0f / l0, inv1 = 1.0f / l1;
    size_t t0 = (tokq + w * 16 + g) * 1024 + zh * 64;
    size_t t1 = t0 + 8 * 1024;
#pragma unroll
    for (int nf = 0; nf < 8; nf++) {
        int c = nf * 8 + tg * 2;
        float o00 = Oacc[nf][0] * inv0, o01 = Oacc[nf][1] * inv0;
        float o10 = Oacc[nf][2] * inv1, o11 = Oacc[nf][3] * inv1;
        __nv_bfloat162 h0 = __float22bfloat162_rn(make_float2(o00, o01));
        __nv_bfloat162 h1 = __float22bfloat162_rn(make_float2(o10, o11));
        __nv_bfloat162 l0v, l1v;
        l0v.x = __float2bfloat16(o00 - __bfloat162float(h0.x));
        l0v.y = __float2bfloat16(o01 - __bfloat162float(h0.y));
        l1v.x = __float2bfloat16(o10 - __bfloat162float(h1.x));
        l1v.y = __float2bfloat16(o11 - __bfloat162float(h1.y));
        *reinterpret_cast<__nv_bfloat162*>(aoh + t0 + c) = h0;
        *reinterpret_cast<__nv_bfloat162*>(aol + t0 + c) = l0v;
        *reinterpret_cast<__nv_bfloat162*>(aoh + t1 + c) = h1;
        *reinterpret_cast<__nv_bfloat162*>(aol + t1 + c) = l1v;
    }
}

// ---------------- launcher ----------------
extern "C" void kernel_launch(void* const* d_in, const int* in_sizes, int n_in,
                              void* d_out, int out_size)
{
    const float* x      = (const float*)d_in[0];
    const float* t_emb  = (const float*)d_in[1];
    const float* rel    = (const float*)d_in[2];
    const int*   amask  = (const int*)d_in[3];
    const float* w_ada  = (const float*)d_in[4];
    const float* b_ada  = (const float*)d_in[5];
    const float* g1     = (const float*)d_in[6];
    const float* be1    = (const float*)d_in[7];
    const float* g2     = (const float*)d_in[8];
    const float* be2    = (const float*)d_in[9];
    const float* w_qkv  = (const float*)d_in[10];
    const float* b_qkv  = (const float*)d_in[11];
    const float* w_proj = (const float*)d_in[12];
    const float* b_proj = (const float*)d_in[13];
    const float* w_rp1  = (const float*)d_in[14];
    const float* b_rp1  = (const float*)d_in[15];
    const float* w_rp2  = (const float*)d_in[16];
    const float* b_rp2  = (const float*)d_in[17];
    const float* w_fc1  = (const float*)d_in[18];
    const float* b_fc1  = (const float*)d_in[19];
    const float* w_fc2  = (const float*)d_in[20];
    const float* b_fc2  = (const float*)d_in[21];
    float* out = (float*)d_out;

    float *mod, *att, *x1;
    __nv_bfloat16 *xnh, *xnl, *qph, *qpl, *aoh, *aol, *hh, *hl;
    __nv_bfloat16 *wqkvh, *wqkvl, *wprojh, *wprojl, *wfc1h, *wfc1l, *wfc2h, *wfc2l;
    cudaGetSymbolAddress((void**)&mod, g_mod);
    cudaGetSymbolAddress((void**)&att, g_att);
    cudaGetSymbolAddress((void**)&x1,  g_x1);
    cudaGetSymbolAddress((void**)&xnh, g_xnh);
    cudaGetSymbolAddress((void**)&xnl, g_xnl);
    cudaGetSymbolAddress((void**)&qph, g_qkvph);
    cudaGetSymbolAddress((void**)&qpl, g_qkvpl);
    cudaGetSymbolAddress((void**)&aoh, g_aoh);
    cudaGetSymbolAddress((void**)&aol, g_aol);
    cudaGetSymbolAddress((void**)&hh,  g_hh);
    cudaGetSymbolAddress((void**)&hl,  g_hl);
    cudaGetSymbolAddress((void**)&wqkvh, g_wqkvh);
    cudaGetSymbolAddress((void**)&wqkvl, g_wqkvl);
    cudaGetSymbolAddress((void**)&wprojh, g_wprojh);
    cudaGetSymbolAddress((void**)&wprojl, g_wprojl);
    cudaGetSymbolAddress((void**)&wfc1h, g_wfc1h);
    cudaGetSymbolAddress((void**)&wfc1l, g_wfc1l);
    cudaGetSymbolAddress((void**)&wfc2h, g_wfc2h);
    cudaGetSymbolAddress((void**)&wfc2l, g_wfc2l);

    constexpr int SM2 = HGDims<2>::SMEM;   // 81920
    constexpr int SM1 = HGDims<1>::SMEM;   // 61440
    cudaFuncSetAttribute(hmma_gemm<TEPI_BIASP, 2>,   cudaFuncAttributeMaxDynamicSharedMemorySize, SM2);
    cudaFuncSetAttribute(hmma_gemm<TEPI_GELUP, 2>,   cudaFuncAttributeMaxDynamicSharedMemorySize, SM2);
    cudaFuncSetAttribute(hmma_gemm<TEPI_RESGATE, 1>, cudaFuncAttributeMaxDynamicSharedMemorySize, SM1);
    cudaFuncSetAttribute(fused_attn,                 cudaFuncAttributeMaxDynamicSharedMemorySize, FA_SMEM);

    // weight splits
    split_kernel<<<3072, 256>>>(w_qkv,  wqkvh,  wqkvl,  3072 * 1024 / 4);
    split_kernel<<<1024, 256>>>(w_proj, wprojh, wprojl, 1024 * 1024 / 4);
    split_kernel<<<4096, 256>>>(w_fc1,  wfc1h,  wfc1l,  4096 * 1024 / 4);
    split_kernel<<<4096, 256>>>(w_fc2,  wfc2h,  wfc2l,  4096 * 1024 / 4);

    // 1. adaLN modulation
    ada_kernel<<<768, 256>>>(t_emb, w_ada, b_ada, mod);
    // 2. LN1 + modulate
    ln_mod_kernel<<<2048, 256>>>(x, g1, be1, mod, 0, 1, xnh, xnl);
    // 3. qkv -> bf16 pairs
    hmma_gemm<TEPI_BIASP, 2><<<dim3(24, 16), 256, SM2>>>(
        xnh, xnl, 1024, wqkvh, wqkvl, 1024, nullptr, 0, 1024,
        b_qkv, nullptr, nullptr, qph, qpl, 3072);
    // 4. rel-pos bias
    relpos_kernel<<<4096, 256>>>(rel, w_rp1, b_rp1, w_rp2, b_rp2, att);
    // 5. fused attention -> ao pairs
    fused_attn<<<dim3(64, 4), 256, FA_SMEM>>>(qph, qpl, att, amask, aoh, aol);
    // 6. proj + gated residual (BM=64 -> 256 CTAs)
    hmma_gemm<TEPI_RESGATE, 1><<<dim3(8, 32), 256, SM1>>>(
        aoh, aol, 1024, wprojh, wprojl, 1024, x1, 1024, 1024,
        b_proj, x, mod + 2048, nullptr, nullptr, 0);
    // 7. LN2 + modulate
    ln_mod_kernel<<<2048, 256>>>(x1, g2, be2, mod, 3, 4, xnh, xnl);
    // 8. fc1 + gelu -> pairs
    hmma_gemm<TEPI_GELUP, 2><<<dim3(32, 16), 256, SM2>>>(
        xnh, xnl, 1024, wfc1h, wfc1l, 1024, nullptr, 0, 1024,
        b_fc1, nullptr, nullptr, hh, hl, 4096);
    // 9. fc2 + gated residual -> out (BM=64 -> 256 CTAs)
    hmma_gemm<TEPI_RESGATE, 1><<<dim3(8, 32), 256, SM1>>>(
        hh, hl, 4096, wfc2h, wfc2l, 4096, out, 1024, 4096,
        b_fc2, x1, mod + 5120, nullptr, nullptr, 0);
}